// round 2
// baseline (speedup 1.0000x reference)
#include <cuda_runtime.h>
#include <cuda_bf16.h>
#include <math.h>

// Problem constants (VSSOnewayLayer): B=8, L=2048, D=256, DIN=512, N=64, P=64, H=8
#define BB 8
#define LL 2048
#define DD 256
#define DIN 512
#define NN 64
#define PP 64
#define HH 8
#define ROWS (BB*LL)          // 16384
#define XPROJ_N (HH + 2*NN)   // 136

// ---------------- scratch (device globals; no allocation allowed) -------------
__device__ float  g_xln[ROWS*DD];
__device__ float  g_u0 [ROWS*DIN];
__device__ float  g_u  [ROWS*DIN];
__device__ float  g_dbc[ROWS*XPROJ_N];
__device__ float2 g_dd [ROWS*HH];
__device__ float  g_y  [ROWS*DIN];
__device__ float  g_yln[ROWS*DIN];

// ---------------- helpers ----------------------------------------------------
__device__ __forceinline__ unsigned smem_u32(const void* p) {
    return (unsigned)__cvta_generic_to_shared(p);
}

// ---------------- LayerNorm (last-dim DN, 256 threads) ------------------------
template<int DN>
__global__ void ln_kernel(const float* __restrict__ x, const float* __restrict__ w,
                          const float* __restrict__ b, float* __restrict__ out) {
    constexpr int E = DN / 256;
    int row = blockIdx.x;
    const float* xr = x + (size_t)row * DN;
    float v[E];
    float s = 0.f, s2 = 0.f;
#pragma unroll
    for (int e = 0; e < E; e++) {
        v[e] = xr[threadIdx.x + e*256];
        s  += v[e];
        s2 += v[e]*v[e];
    }
    // warp reduce
#pragma unroll
    for (int off = 16; off > 0; off >>= 1) {
        s  += __shfl_xor_sync(0xFFFFFFFFu, s,  off);
        s2 += __shfl_xor_sync(0xFFFFFFFFu, s2, off);
    }
    __shared__ float rs[8], rs2[8];
    int wid = threadIdx.x >> 5, lane = threadIdx.x & 31;
    if (lane == 0) { rs[wid] = s; rs2[wid] = s2; }
    __syncthreads();
    __shared__ float mean_s, rstd_s;
    if (threadIdx.x == 0) {
        float S = 0.f, S2 = 0.f;
#pragma unroll
        for (int i = 0; i < 8; i++) { S += rs[i]; S2 += rs2[i]; }
        float m = S / DN;
        float var = S2 / DN - m*m;
        mean_s = m;
        rstd_s = rsqrtf(var + 1e-5f);
    }
    __syncthreads();
    float m = mean_s, r = rstd_s;
    float* orow = out + (size_t)row * DN;
#pragma unroll
    for (int e = 0; e < E; e++) {
        int i = threadIdx.x + e*256;
        orow[i] = (v[e] - m) * r * w[i] + b[i];
    }
}

// ---------------- depthwise conv3 (SAME, zero pad) + exact GELU ---------------
__global__ void conv_gelu_kernel(const float* __restrict__ u0, const float* __restrict__ cw,
                                 const float* __restrict__ cb, float* __restrict__ u) {
    int row = blockIdx.x;          // b*L + l
    int l = row & (LL - 1);
    int c = threadIdx.x;
    size_t base = (size_t)row * DIN + c;
    float mid = u0[base];
    float lft = (l > 0)      ? u0[base - DIN] : 0.f;
    float rgt = (l < LL - 1) ? u0[base + DIN] : 0.f;
    float w0 = cw[c*3+0], w1 = cw[c*3+1], w2 = cw[c*3+2];
    float z = fmaf(lft, w0, fmaf(mid, w1, fmaf(rgt, w2, cb[c])));
    u[base] = 0.5f * z * (1.f + erff(z * 0.70710678118654752440f));
}

// ---------------- dt = softplus(dbc_h + bias), decay = exp(dt * -exp(A_log)) --
__global__ void dtdec_kernel(const float* __restrict__ dbc, const float* __restrict__ dt_bias,
                             const float* __restrict__ A_log, float2* __restrict__ dd) {
    int i = blockIdx.x * blockDim.x + threadIdx.x;
    if (i >= ROWS * HH) return;
    int h = i & (HH - 1);
    int row = i >> 3;
    float z = dbc[(size_t)row * XPROJ_N + h] + dt_bias[h];
    float dt = (z > 20.f) ? z : log1pf(expf(z));
    float dec = expf(dt * (-expf(A_log[h])));
    dd[i] = make_float2(dt, dec);
}

// ---------------- fp32 shared-tiled GEMM: C = A[MxK] @ W[KxN] (+src) ----------
template<bool ADD>
__global__ void gemm_kernel(const float* __restrict__ A, const float* __restrict__ W,
                            float* __restrict__ C, const float* __restrict__ add,
                            int M, int N, int K) {
    __shared__ float As[32][65];   // [k][m], padded
    __shared__ float Bs[32][64];   // [k][n]
    int tid = threadIdx.x;
    int tx = tid & 15, ty = tid >> 4;
    int m0 = blockIdx.y * 64, n0 = blockIdx.x * 64;
    bool nfull = (n0 + 64 <= N);
    float acc[4][4];
#pragma unroll
    for (int i = 0; i < 4; i++)
#pragma unroll
        for (int j = 0; j < 4; j++) acc[i][j] = 0.f;

    for (int k0 = 0; k0 < K; k0 += 32) {
        {   // A tile: 64 rows x 32 k, store transposed
            int r = tid >> 3, c4 = tid & 7;
#pragma unroll
            for (int rr = r; rr < 64; rr += 32) {
                float4 av = *(const float4*)(A + (size_t)(m0 + rr) * K + k0 + c4*4);
                As[c4*4+0][rr] = av.x; As[c4*4+1][rr] = av.y;
                As[c4*4+2][rr] = av.z; As[c4*4+3][rr] = av.w;
            }
        }
        {   // W tile: 32 k x 64 cols
            int kk = tid >> 4, c4 = tid & 15;
#pragma unroll
            for (int k2 = kk; k2 < 32; k2 += 16) {
                int col = n0 + c4*4;
                float4 wv;
                if (nfull || col + 3 < N)
                    wv = *(const float4*)(W + (size_t)(k0 + k2) * N + col);
                else
                    wv = make_float4(0.f, 0.f, 0.f, 0.f);
                *(float4*)&Bs[k2][c4*4] = wv;
            }
        }
        __syncthreads();
#pragma unroll
        for (int k = 0; k < 32; k++) {
            float a0 = As[k][ty*4+0], a1 = As[k][ty*4+1];
            float a2 = As[k][ty*4+2], a3 = As[k][ty*4+3];
            float4 bv = *(const float4*)&Bs[k][tx*4];
            acc[0][0] = fmaf(a0, bv.x, acc[0][0]); acc[0][1] = fmaf(a0, bv.y, acc[0][1]);
            acc[0][2] = fmaf(a0, bv.z, acc[0][2]); acc[0][3] = fmaf(a0, bv.w, acc[0][3]);
            acc[1][0] = fmaf(a1, bv.x, acc[1][0]); acc[1][1] = fmaf(a1, bv.y, acc[1][1]);
            acc[1][2] = fmaf(a1, bv.z, acc[1][2]); acc[1][3] = fmaf(a1, bv.w, acc[1][3]);
            acc[2][0] = fmaf(a2, bv.x, acc[2][0]); acc[2][1] = fmaf(a2, bv.y, acc[2][1]);
            acc[2][2] = fmaf(a2, bv.z, acc[2][2]); acc[2][3] = fmaf(a2, bv.w, acc[2][3]);
            acc[3][0] = fmaf(a3, bv.x, acc[3][0]); acc[3][1] = fmaf(a3, bv.y, acc[3][1]);
            acc[3][2] = fmaf(a3, bv.z, acc[3][2]); acc[3][3] = fmaf(a3, bv.w, acc[3][3]);
        }
        __syncthreads();
    }
#pragma unroll
    for (int i = 0; i < 4; i++) {
        int m = m0 + ty*4 + i;
#pragma unroll
        for (int j = 0; j < 4; j++) {
            int n = n0 + tx*4 + j;
            if (n < N) {
                float v = acc[i][j];
                if (ADD) v += add[(size_t)m * N + n];
                C[(size_t)m * N + n] = v;
            }
        }
    }
}

// ---------------- selective scan: one CTA per (b,h) ---------------------------
// state h[p][n] (64x64) in registers: thread t -> p = t>>2, n-chunk = (t&3)*16
// h = h*decay + (dt*x_p)*B_n ; y_p = sum_n h*C_n ; out = y + x_p*Ds_h
// cp.async double-buffered 8-step chunks.
__global__ void scan_kernel(const float* __restrict__ u, const float* __restrict__ dbc,
                            const float2* __restrict__ dd, const float* __restrict__ Ds,
                            float* __restrict__ y) {
    const int b = blockIdx.x >> 3, h = blockIdx.x & 7;
    const int tid = threadIdx.x;
    const int p = tid >> 2, q = tid & 3, n0 = q * 16;

    __shared__ alignas(16) float  us [2][8][64];
    __shared__ alignas(16) float  Bsm[2][8][64];
    __shared__ alignas(16) float  Csm[2][8][64];
    __shared__ alignas(16) float2 dds[2][8];

    const size_t rowbase = (size_t)b * LL;
    float st[16];
#pragma unroll
    for (int i = 0; i < 16; i++) st[i] = 0.f;
    const float Dh = Ds[h];

    auto issue = [&](int chunk, int bi) {
        int l0 = chunk * 8;
        for (int t = tid; t < 392; t += 256) {
            if (t < 384) {
                int reg = t >> 7;            // 0: u slice, 1: B, 2: C
                int rr  = t & 127;
                int j = rr >> 4, f = rr & 15;
                const float* src;
                float* dst;
                if (reg == 0)      { src = u   + (rowbase + l0 + j)*DIN     + h*64 + f*4; dst = &us [bi][j][f*4]; }
                else if (reg == 1) { src = dbc + (rowbase + l0 + j)*XPROJ_N + HH   + f*4; dst = &Bsm[bi][j][f*4]; }
                else               { src = dbc + (rowbase + l0 + j)*XPROJ_N + HH+NN+ f*4; dst = &Csm[bi][j][f*4]; }
                asm volatile("cp.async.ca.shared.global [%0], [%1], 16;\n"
                             :: "r"(smem_u32(dst)), "l"(src) : "memory");
            } else {
                int j = t - 384;
                const float2* src = dd + (rowbase + l0 + j)*HH + h;
                asm volatile("cp.async.ca.shared.global [%0], [%1], 8;\n"
                             :: "r"(smem_u32(&dds[bi][j])), "l"(src) : "memory");
            }
        }
        asm volatile("cp.async.commit_group;\n" ::: "memory");
    };

    issue(0, 0);
    const int nch = LL / 8;
    for (int c = 0; c < nch; c++) {
        int bi = c & 1;
        if (c + 1 < nch) {
            issue(c + 1, bi ^ 1);
            asm volatile("cp.async.wait_group 1;\n" ::: "memory");
        } else {
            asm volatile("cp.async.wait_group 0;\n" ::: "memory");
        }
        __syncthreads();
#pragma unroll
        for (int j = 0; j < 8; j++) {
            float2 d2 = dds[bi][j];
            float xp  = us[bi][j][p];
            float a   = d2.x * xp;
            float dec = d2.y;
            const float4* B4 = (const float4*)&Bsm[bi][j][n0];
            const float4* C4 = (const float4*)&Csm[bi][j][n0];
            float acc = 0.f;
#pragma unroll
            for (int i = 0; i < 4; i++) {
                float4 bq = B4[i];
                float4 cq = C4[i];
                st[i*4+0] = fmaf(st[i*4+0], dec, a*bq.x); acc = fmaf(st[i*4+0], cq.x, acc);
                st[i*4+1] = fmaf(st[i*4+1], dec, a*bq.y); acc = fmaf(st[i*4+1], cq.y, acc);
                st[i*4+2] = fmaf(st[i*4+2], dec, a*bq.z); acc = fmaf(st[i*4+2], cq.z, acc);
                st[i*4+3] = fmaf(st[i*4+3], dec, a*bq.w); acc = fmaf(st[i*4+3], cq.w, acc);
            }
            acc += __shfl_xor_sync(0xFFFFFFFFu, acc, 1);
            acc += __shfl_xor_sync(0xFFFFFFFFu, acc, 2);
            if (q == 0)
                y[(rowbase + c*8 + j)*DIN + h*64 + p] = fmaf(xp, Dh, acc);
        }
        __syncthreads();
    }
}

// ---------------- launch ------------------------------------------------------
extern "C" void kernel_launch(void* const* d_in, const int* in_sizes, int n_in,
                              void* d_out, int out_size) {
    const float* src     = (const float*)d_in[0];
    const float* ln_w    = (const float*)d_in[1];
    const float* ln_b    = (const float*)d_in[2];
    const float* W_in    = (const float*)d_in[3];
    const float* conv_w  = (const float*)d_in[4];
    const float* conv_b  = (const float*)d_in[5];
    const float* W_xproj = (const float*)d_in[6];
    const float* dt_bias = (const float*)d_in[7];
    const float* A_log   = (const float*)d_in[8];
    const float* Ds      = (const float*)d_in[9];
    const float* oln_w   = (const float*)d_in[10];
    const float* oln_b   = (const float*)d_in[11];
    const float* W_out   = (const float*)d_in[12];
    float* out = (float*)d_out;

    float  *p_xln, *p_u0, *p_u, *p_dbc, *p_y, *p_yln;
    float2 *p_dd;
    cudaGetSymbolAddress((void**)&p_xln, g_xln);
    cudaGetSymbolAddress((void**)&p_u0,  g_u0);
    cudaGetSymbolAddress((void**)&p_u,   g_u);
    cudaGetSymbolAddress((void**)&p_dbc, g_dbc);
    cudaGetSymbolAddress((void**)&p_dd,  g_dd);
    cudaGetSymbolAddress((void**)&p_y,   g_y);
    cudaGetSymbolAddress((void**)&p_yln, g_yln);

    // 1. input LN
    ln_kernel<DD><<<ROWS, 256>>>(src, ln_w, ln_b, p_xln);
    // 2. u0 = xln @ W_in  (16384 x 512, K=256)
    gemm_kernel<false><<<dim3(DIN/64, ROWS/64), 256>>>(p_xln, W_in, p_u0, nullptr, ROWS, DIN, DD);
    // 3. depthwise conv3 + GELU
    conv_gelu_kernel<<<ROWS, DIN>>>(p_u0, conv_w, conv_b, p_u);
    // 4. dbc = u @ W_xproj (16384 x 136, K=512)
    gemm_kernel<false><<<dim3((XPROJ_N + 63)/64, ROWS/64), 256>>>(p_u, W_xproj, p_dbc, nullptr, ROWS, XPROJ_N, DIN);
    // 5. dt / decay
    dtdec_kernel<<<(ROWS*HH + 255)/256, 256>>>(p_dbc, dt_bias, A_log, p_dd);
    // 6. selective scan (+ Ds skip)
    scan_kernel<<<BB*HH, 256>>>(p_u, p_dbc, p_dd, Ds, p_y);
    // 7. output LN
    ln_kernel<DIN><<<ROWS, 256>>>(p_y, oln_w, oln_b, p_yln);
    // 8. out = src + yln @ W_out (16384 x 256, K=512)
    gemm_kernel<true><<<dim3(DD/64, ROWS/64), 256>>>(p_yln, W_out, out, src, ROWS, DD, DIN);
}

// round 5
// speedup vs baseline: 2.1204x; 2.1204x over previous
#include <cuda_runtime.h>
#include <cuda_bf16.h>
#include <math.h>

// Problem constants (VSSOnewayLayer): B=8, L=2048, D=256, DIN=512, N=64, P=64, H=8
#define BB 8
#define LL 2048
#define DD 256
#define DIN 512
#define NN 64
#define PP 64
#define HH 8
#define ROWS (BB*LL)          // 16384
#define XPROJ_N (HH + 2*NN)   // 136

// ---------------- scratch (device globals; no allocation allowed) -------------
__device__ float  g_xln[ROWS*DD];
__device__ float  g_u0 [ROWS*DIN];
__device__ float  g_u  [ROWS*DIN];
__device__ float  g_dbc[ROWS*XPROJ_N];
__device__ float2 g_dd [ROWS*HH];
__device__ float  g_y0 [ROWS*DIN];
__device__ float  g_y1 [ROWS*DIN];
__device__ float  g_yln[ROWS*DIN];

// ---------------- helpers ----------------------------------------------------
__device__ __forceinline__ unsigned smem_u32(const void* p) {
    return (unsigned)__cvta_generic_to_shared(p);
}

// ---------------- LayerNorm (last-dim DN, 256 threads) ------------------------
template<int DN, bool SUM2>
__global__ void ln_kernel(const float* __restrict__ x, const float* __restrict__ x2,
                          const float* __restrict__ w, const float* __restrict__ b,
                          float* __restrict__ out) {
    constexpr int E = DN / 256;
    int row = blockIdx.x;
    const float* xr = x + (size_t)row * DN;
    const float* xr2 = SUM2 ? (x2 + (size_t)row * DN) : nullptr;
    float v[E];
    float s = 0.f, s2 = 0.f;
#pragma unroll
    for (int e = 0; e < E; e++) {
        v[e] = xr[threadIdx.x + e*256];
        if (SUM2) v[e] += xr2[threadIdx.x + e*256];
        s  += v[e];
        s2 += v[e]*v[e];
    }
#pragma unroll
    for (int off = 16; off > 0; off >>= 1) {
        s  += __shfl_xor_sync(0xFFFFFFFFu, s,  off);
        s2 += __shfl_xor_sync(0xFFFFFFFFu, s2, off);
    }
    __shared__ float rs[8], rs2[8];
    int wid = threadIdx.x >> 5, lane = threadIdx.x & 31;
    if (lane == 0) { rs[wid] = s; rs2[wid] = s2; }
    __syncthreads();
    __shared__ float mean_s, rstd_s;
    if (threadIdx.x == 0) {
        float S = 0.f, S2 = 0.f;
#pragma unroll
        for (int i = 0; i < 8; i++) { S += rs[i]; S2 += rs2[i]; }
        float m = S / DN;
        float var = S2 / DN - m*m;
        mean_s = m;
        rstd_s = rsqrtf(var + 1e-5f);
    }
    __syncthreads();
    float m = mean_s, r = rstd_s;
    float* orow = out + (size_t)row * DN;
#pragma unroll
    for (int e = 0; e < E; e++) {
        int i = threadIdx.x + e*256;
        orow[i] = (v[e] - m) * r * w[i] + b[i];
    }
}

// ---------------- depthwise conv3 (SAME, zero pad) + exact GELU ---------------
__global__ void conv_gelu_kernel(const float* __restrict__ u0, const float* __restrict__ cw,
                                 const float* __restrict__ cb, float* __restrict__ u) {
    int row = blockIdx.x;          // b*L + l
    int l = row & (LL - 1);
    int c = threadIdx.x;
    size_t base = (size_t)row * DIN + c;
    float mid = u0[base];
    float lft = (l > 0)      ? u0[base - DIN] : 0.f;
    float rgt = (l < LL - 1) ? u0[base + DIN] : 0.f;
    float w0 = cw[c*3+0], w1 = cw[c*3+1], w2 = cw[c*3+2];
    float z = fmaf(lft, w0, fmaf(mid, w1, fmaf(rgt, w2, cb[c])));
    u[base] = 0.5f * z * (1.f + erff(z * 0.70710678118654752440f));
}

// ---------------- dt = softplus(dbc_h + bias), decay = exp(dt * -exp(A_log)) --
__global__ void dtdec_kernel(const float* __restrict__ dbc, const float* __restrict__ dt_bias,
                             const float* __restrict__ A_log, float2* __restrict__ dd) {
    int i = blockIdx.x * blockDim.x + threadIdx.x;
    if (i >= ROWS * HH) return;
    int h = i & (HH - 1);
    int row = i >> 3;
    float z = dbc[(size_t)row * XPROJ_N + h] + dt_bias[h];
    float dt = (z > 20.f) ? z : log1pf(expf(z));
    float dec = expf(dt * (-expf(A_log[h])));
    dd[i] = make_float2(dt, dec);
}

// ---------------- TF32 tensor-core GEMM: C = A[MxK] @ W[KxN] (+src) -----------
// CTA tile 128x64x32, 8 warps (4M x 2N), warp tile 32x32 via m16n8k8 frags.
// smem: As [128][36] (pad 4 -> conflict-free frag loads), Bs [32][72] (pad 8).
#define BM 128
#define BN 64
#define BKK 32
#define PADA 36
#define PADB 72
#define GEMM_SMEM ((2*BM*PADA + 2*BKK*PADB) * 4)

template<bool ADD>
__global__ void __launch_bounds__(256, 2)
mma_gemm(const float* __restrict__ A, const float* __restrict__ W,
         float* __restrict__ C, const float* __restrict__ add,
         int M, int N, int K) {
    extern __shared__ float sm[];
    float* As = sm;                       // [2][BM*PADA]
    float* Bs = sm + 2*BM*PADA;           // [2][BKK*PADB]
    const int tid = threadIdx.x;
    const int m0 = blockIdx.y * BM, n0 = blockIdx.x * BN;
    const int warp = tid >> 5, lane = tid & 31;
    const int wm = (warp & 3) * 32, wn = (warp >> 2) * 32;
    const int gr = lane >> 2, tc = lane & 3;

    float c[2][4][4];
#pragma unroll
    for (int i = 0; i < 2; i++)
#pragma unroll
        for (int j = 0; j < 4; j++)
#pragma unroll
            for (int r = 0; r < 4; r++) c[i][j][r] = 0.f;

    auto load_tiles = [&](int k0, int buf) {
        float* as = As + buf * BM * PADA;
        float* bs = Bs + buf * BKK * PADB;
#pragma unroll
        for (int i = 0; i < 4; i++) {                 // A: 128x32 = 1024 float4
            int idx = tid + i * 256;
            int m = idx >> 3, kq = (idx & 7) * 4;
            const float* src = A + (size_t)(m0 + m) * K + k0 + kq;
            asm volatile("cp.async.ca.shared.global [%0], [%1], 16;\n"
                         :: "r"(smem_u32(as + m*PADA + kq)), "l"(src) : "memory");
        }
#pragma unroll
        for (int i = 0; i < 2; i++) {                 // B: 32x64 = 512 float4
            int idx = tid + i * 256;
            int k = idx >> 4, nq = (idx & 15) * 4;
            int col = n0 + nq;
            const float* src = W + (size_t)(k0 + k) * N + col;
            int sz = (col + 3 < N) ? 16 : 0;          // N % 4 == 0 always
            if (sz == 0) src = W;                     // keep pointer valid
            asm volatile("cp.async.ca.shared.global [%0], [%1], 16, %2;\n"
                         :: "r"(smem_u32(bs + k*PADB + nq)), "l"(src), "r"(sz) : "memory");
        }
        asm volatile("cp.async.commit_group;\n" ::: "memory");
    };

    load_tiles(0, 0);
    const int nk = K / BKK;
    for (int kt = 0; kt < nk; kt++) {
        int buf = kt & 1;
        if (kt + 1 < nk) {
            load_tiles((kt + 1) * BKK, buf ^ 1);
            asm volatile("cp.async.wait_group 1;\n" ::: "memory");
        } else {
            asm volatile("cp.async.wait_group 0;\n" ::: "memory");
        }
        __syncthreads();
        const float* as = As + buf * BM * PADA;
        const float* bs = Bs + buf * BKK * PADB;
#pragma unroll
        for (int ks = 0; ks < 4; ks++) {
            const int kk = ks * 8;
            unsigned a[2][4], bf[4][2];
#pragma unroll
            for (int i = 0; i < 2; i++) {
                const float* ap = as + (wm + i*16 + gr) * PADA + kk + tc;
                a[i][0] = __float_as_uint(ap[0]);
                a[i][1] = __float_as_uint(ap[8*PADA]);
                a[i][2] = __float_as_uint(ap[4]);
                a[i][3] = __float_as_uint(ap[8*PADA + 4]);
            }
#pragma unroll
            for (int j = 0; j < 4; j++) {
                const float* bp = bs + (kk + tc) * PADB + wn + j*8 + gr;
                bf[j][0] = __float_as_uint(bp[0]);
                bf[j][1] = __float_as_uint(bp[4*PADB]);
            }
#pragma unroll
            for (int i = 0; i < 2; i++)
#pragma unroll
                for (int j = 0; j < 4; j++)
                    asm volatile(
                        "mma.sync.aligned.m16n8k8.row.col.f32.tf32.tf32.f32 "
                        "{%0,%1,%2,%3}, {%4,%5,%6,%7}, {%8,%9}, {%0,%1,%2,%3};"
                        : "+f"(c[i][j][0]), "+f"(c[i][j][1]),
                          "+f"(c[i][j][2]), "+f"(c[i][j][3])
                        : "r"(a[i][0]), "r"(a[i][1]), "r"(a[i][2]), "r"(a[i][3]),
                          "r"(bf[j][0]), "r"(bf[j][1]));
        }
        __syncthreads();
    }

#pragma unroll
    for (int i = 0; i < 2; i++) {
        int mr = m0 + wm + i*16 + gr;
#pragma unroll
        for (int j = 0; j < 4; j++) {
            int col = n0 + wn + j*8 + tc*2;
            if (col < N) {
                size_t o0 = (size_t)mr * N + col;
                size_t o1 = (size_t)(mr + 8) * N + col;
                float v0 = c[i][j][0], v1 = c[i][j][1];
                float v2 = c[i][j][2], v3 = c[i][j][3];
                if (ADD) { v0 += add[o0]; v1 += add[o0+1]; v2 += add[o1]; v3 += add[o1+1]; }
                C[o0] = v0; C[o0+1] = v1; C[o1] = v2; C[o1+1] = v3;
            }
        }
    }
}

// ---------------- selective scan: one CTA per (b,h,n-half) --------------------
// 128 CTAs. state h[p][n-half] (64x32) in regs: thread t -> p = t>>2, 8 n each.
// half 0 writes y0 = x*Ds + sum_n(h*C); half 1 writes y1 = sum_n(h*C).
// Output LN sums y0+y1.
__global__ void scan_kernel(const float* __restrict__ u, const float* __restrict__ dbc,
                            const float2* __restrict__ dd, const float* __restrict__ Ds,
                            float* __restrict__ y0, float* __restrict__ y1) {
    const int bh = blockIdx.x >> 1, half = blockIdx.x & 1;
    const int b = bh >> 3, h = bh & 7;
    const int tid = threadIdx.x;
    const int p = tid >> 2, q = tid & 3, nq = q * 8;

    __shared__ alignas(16) float  us [2][8][64];
    __shared__ alignas(16) float  Bsm[2][8][32];
    __shared__ alignas(16) float  Csm[2][8][32];
    __shared__ alignas(16) float2 dds[2][8];

    const size_t rowbase = (size_t)b * LL;
    float st[8];
#pragma unroll
    for (int i = 0; i < 8; i++) st[i] = 0.f;
    const float Dh = Ds[h];
    const int nb = HH + half * 32;           // B offset within dbc row
    const int nc = HH + NN + half * 32;      // C offset within dbc row

    auto issue = [&](int chunk, int bi) {
        int l0 = chunk * 8;
        for (int t = tid; t < 264; t += 256) {
            if (t < 128) {                    // u slice: 8 x 64 floats
                int j = t >> 4, f = (t & 15) * 4;
                const float* src = u + (rowbase + l0 + j)*DIN + h*64 + f;
                asm volatile("cp.async.ca.shared.global [%0], [%1], 16;\n"
                             :: "r"(smem_u32(&us[bi][j][f])), "l"(src) : "memory");
            } else if (t < 192) {             // B half: 8 x 32
                int r = t - 128; int j = r >> 3, f = (r & 7) * 4;
                const float* src = dbc + (rowbase + l0 + j)*XPROJ_N + nb + f;
                asm volatile("cp.async.ca.shared.global [%0], [%1], 16;\n"
                             :: "r"(smem_u32(&Bsm[bi][j][f])), "l"(src) : "memory");
            } else if (t < 256) {             // C half: 8 x 32
                int r = t - 192; int j = r >> 3, f = (r & 7) * 4;
                const float* src = dbc + (rowbase + l0 + j)*XPROJ_N + nc + f;
                asm volatile("cp.async.ca.shared.global [%0], [%1], 16;\n"
                             :: "r"(smem_u32(&Csm[bi][j][f])), "l"(src) : "memory");
            } else {                          // dt/decay: 8 x float2
                int j = t - 256;
                const float2* src = dd + (rowbase + l0 + j)*HH + h;
                asm volatile("cp.async.ca.shared.global [%0], [%1], 8;\n"
                             :: "r"(smem_u32(&dds[bi][j])), "l"(src) : "memory");
            }
        }
        asm volatile("cp.async.commit_group;\n" ::: "memory");
    };

    issue(0, 0);
    const int nch = LL / 8;
    for (int cix = 0; cix < nch; cix++) {
        int bi = cix & 1;
        if (cix + 1 < nch) {
            issue(cix + 1, bi ^ 1);
            asm volatile("cp.async.wait_group 1;\n" ::: "memory");
        } else {
            asm volatile("cp.async.wait_group 0;\n" ::: "memory");
        }
        __syncthreads();
#pragma unroll
        for (int j = 0; j < 8; j++) {
            float2 d2 = dds[bi][j];
            float xp  = us[bi][j][p];
            float a   = d2.x * xp;
            float dec = d2.y;
            const float4* B4 = (const float4*)&Bsm[bi][j][nq];
            const float4* C4 = (const float4*)&Csm[bi][j][nq];
            float acc = 0.f;
#pragma unroll
            for (int i = 0; i < 2; i++) {
                float4 bq = B4[i];
                float4 cq = C4[i];
                st[i*4+0] = fmaf(st[i*4+0], dec, a*bq.x); acc = fmaf(st[i*4+0], cq.x, acc);
                st[i*4+1] = fmaf(st[i*4+1], dec, a*bq.y); acc = fmaf(st[i*4+1], cq.y, acc);
                st[i*4+2] = fmaf(st[i*4+2], dec, a*bq.z); acc = fmaf(st[i*4+2], cq.z, acc);
                st[i*4+3] = fmaf(st[i*4+3], dec, a*bq.w); acc = fmaf(st[i*4+3], cq.w, acc);
            }
            acc += __shfl_xor_sync(0xFFFFFFFFu, acc, 1);
            acc += __shfl_xor_sync(0xFFFFFFFFu, acc, 2);
            if (q == 0) {
                size_t o = (rowbase + cix*8 + j)*DIN + h*64 + p;
                if (half == 0) y0[o] = fmaf(xp, Dh, acc);
                else           y1[o] = acc;
            }
        }
        __syncthreads();
    }
}

// ---------------- launch ------------------------------------------------------
extern "C" void kernel_launch(void* const* d_in, const int* in_sizes, int n_in,
                              void* d_out, int out_size) {
    const float* src     = (const float*)d_in[0];
    const float* ln_w    = (const float*)d_in[1];
    const float* ln_b    = (const float*)d_in[2];
    const float* W_in    = (const float*)d_in[3];
    const float* conv_w  = (const float*)d_in[4];
    const float* conv_b  = (const float*)d_in[5];
    const float* W_xproj = (const float*)d_in[6];
    const float* dt_bias = (const float*)d_in[7];
    const float* A_log   = (const float*)d_in[8];
    const float* Ds      = (const float*)d_in[9];
    const float* oln_w   = (const float*)d_in[10];
    const float* oln_b   = (const float*)d_in[11];
    const float* W_out   = (const float*)d_in[12];
    float* out = (float*)d_out;

    float  *p_xln, *p_u0, *p_u, *p_dbc, *p_y0, *p_y1, *p_yln;
    float2 *p_dd;
    cudaGetSymbolAddress((void**)&p_xln, g_xln);
    cudaGetSymbolAddress((void**)&p_u0,  g_u0);
    cudaGetSymbolAddress((void**)&p_u,   g_u);
    cudaGetSymbolAddress((void**)&p_dbc, g_dbc);
    cudaGetSymbolAddress((void**)&p_dd,  g_dd);
    cudaGetSymbolAddress((void**)&p_y0,  g_y0);
    cudaGetSymbolAddress((void**)&p_y1,  g_y1);
    cudaGetSymbolAddress((void**)&p_yln, g_yln);

    cudaFuncSetAttribute(mma_gemm<false>, cudaFuncAttributeMaxDynamicSharedMemorySize, GEMM_SMEM);
    cudaFuncSetAttribute(mma_gemm<true>,  cudaFuncAttributeMaxDynamicSharedMemorySize, GEMM_SMEM);

    // 1. input LN
    ln_kernel<DD, false><<<ROWS, 256>>>(src, nullptr, ln_w, ln_b, p_xln);
    // 2. u0 = xln @ W_in  (16384 x 512, K=256)
    mma_gemm<false><<<dim3(DIN/BN, ROWS/BM), 256, GEMM_SMEM>>>(p_xln, W_in, p_u0, nullptr, ROWS, DIN, DD);
    // 3. depthwise conv3 + GELU
    conv_gelu_kernel<<<ROWS, DIN>>>(p_u0, conv_w, conv_b, p_u);
    // 4. dbc = u @ W_xproj (16384 x 136, K=512)
    mma_gemm<false><<<dim3((XPROJ_N + BN - 1)/BN, ROWS/BM), 256, GEMM_SMEM>>>(p_u, W_xproj, p_dbc, nullptr, ROWS, XPROJ_N, DIN);
    // 5. dt / decay
    dtdec_kernel<<<(ROWS*HH + 255)/256, 256>>>(p_dbc, dt_bias, A_log, p_dd);
    // 6. selective scan, N split across 2 CTAs per (b,h)
    scan_kernel<<<BB*HH*2, 256>>>(p_u, p_dbc, p_dd, Ds, p_y0, p_y1);
    // 7. output LN over (y0 + y1)
    ln_kernel<DIN, true><<<ROWS, 256>>>(p_y0, p_y1, oln_w, oln_b, p_yln);
    // 8. out = src + yln @ W_out (16384 x 256, K=512)
    mma_gemm<true><<<dim3(DD/BN, ROWS/BM), 256, GEMM_SMEM>>>(p_yln, W_out, out, src, ROWS, DD, DIN);
}

// round 8
// speedup vs baseline: 2.2081x; 1.0413x over previous
#include <cuda_runtime.h>
#include <cuda_bf16.h>
#include <math.h>

// Problem constants (VSSOnewayLayer): B=8, L=2048, D=256, DIN=512, N=64, P=64, H=8
#define BB 8
#define LL 2048
#define DD 256
#define DIN 512
#define NN 64
#define PP 64
#define HH 8
#define ROWS (BB*LL)          // 16384
#define XPROJ_N (HH + 2*NN)   // 136

// ---------------- scratch (device globals; no allocation allowed) -------------
__device__ float  g_xln[ROWS*DD];
__device__ float  g_u0 [ROWS*DIN];
__device__ float  g_u  [ROWS*DIN];
__device__ float  g_dbc[ROWS*XPROJ_N];
__device__ float2 g_dd [ROWS*HH];
__device__ float  g_y0 [ROWS*DIN];
__device__ float  g_y1 [ROWS*DIN];
__device__ float  g_yln[ROWS*DIN];

// ---------------- helpers ----------------------------------------------------
__device__ __forceinline__ unsigned smem_u32(const void* p) {
    return (unsigned)__cvta_generic_to_shared(p);
}
__device__ __forceinline__ unsigned long long pack2(float lo, float hi) {
    unsigned long long r;
    asm("mov.b64 %0, {%1, %2};" : "=l"(r) : "f"(lo), "f"(hi));
    return r;
}
__device__ __forceinline__ unsigned long long mul2(unsigned long long a, unsigned long long b) {
    unsigned long long r;
    asm("mul.rn.f32x2 %0, %1, %2;" : "=l"(r) : "l"(a), "l"(b));
    return r;
}
__device__ __forceinline__ unsigned long long fma2(unsigned long long a, unsigned long long b,
                                                   unsigned long long c) {
    unsigned long long r;
    asm("fma.rn.f32x2 %0, %1, %2, %3;" : "=l"(r) : "l"(a), "l"(b), "l"(c));
    return r;
}
__device__ __forceinline__ float pair_sum(unsigned long long v) {
    float lo, hi;
    asm("mov.b64 {%0, %1}, %2;" : "=f"(lo), "=f"(hi) : "l"(v));
    return lo + hi;
}

// ---------------- LayerNorm (last-dim DN, 256 threads) ------------------------
template<int DN, bool SUM2>
__global__ void ln_kernel(const float* __restrict__ x, const float* __restrict__ x2,
                          const float* __restrict__ w, const float* __restrict__ b,
                          float* __restrict__ out) {
    constexpr int E = DN / 256;
    int row = blockIdx.x;
    const float* xr = x + (size_t)row * DN;
    const float* xr2 = SUM2 ? (x2 + (size_t)row * DN) : nullptr;
    float v[E];
    float s = 0.f, s2 = 0.f;
#pragma unroll
    for (int e = 0; e < E; e++) {
        v[e] = xr[threadIdx.x + e*256];
        if (SUM2) v[e] += xr2[threadIdx.x + e*256];
        s  += v[e];
        s2 += v[e]*v[e];
    }
#pragma unroll
    for (int off = 16; off > 0; off >>= 1) {
        s  += __shfl_xor_sync(0xFFFFFFFFu, s,  off);
        s2 += __shfl_xor_sync(0xFFFFFFFFu, s2, off);
    }
    __shared__ float rs[8], rs2[8];
    int wid = threadIdx.x >> 5, lane = threadIdx.x & 31;
    if (lane == 0) { rs[wid] = s; rs2[wid] = s2; }
    __syncthreads();
    __shared__ float mean_s, rstd_s;
    if (threadIdx.x == 0) {
        float S = 0.f, S2 = 0.f;
#pragma unroll
        for (int i = 0; i < 8; i++) { S += rs[i]; S2 += rs2[i]; }
        float m = S / DN;
        float var = S2 / DN - m*m;
        mean_s = m;
        rstd_s = rsqrtf(var + 1e-5f);
    }
    __syncthreads();
    float m = mean_s, r = rstd_s;
    float* orow = out + (size_t)row * DN;
#pragma unroll
    for (int e = 0; e < E; e++) {
        int i = threadIdx.x + e*256;
        orow[i] = (v[e] - m) * r * w[i] + b[i];
    }
}

// ---------------- depthwise conv3 (SAME, zero pad) + exact GELU ---------------
// 128 threads, 4 channels each (float4 path). Weights copied into a REAL
// array (register-resident under full unroll) — no cross-local indexing UB.
__global__ void conv_gelu_kernel(const float* __restrict__ u0, const float* __restrict__ cw,
                                 const float* __restrict__ cb, float* __restrict__ u) {
    int row = blockIdx.x;          // b*L + l
    int l = row & (LL - 1);
    int c4 = threadIdx.x * 4;
    size_t base = (size_t)row * DIN + c4;
    float4 mid = *(const float4*)(u0 + base);
    float4 lft = (l > 0)      ? *(const float4*)(u0 + base - DIN) : make_float4(0,0,0,0);
    float4 rgt = (l < LL - 1) ? *(const float4*)(u0 + base + DIN) : make_float4(0,0,0,0);
    float4 bb = *(const float4*)(cb + c4);

    float wf[12];
    *(float4*)&wf[0] = *(const float4*)(cw + c4*3);
    *(float4*)&wf[4] = *(const float4*)(cw + c4*3 + 4);
    *(float4*)&wf[8] = *(const float4*)(cw + c4*3 + 8);

    float lv[4] = {lft.x, lft.y, lft.z, lft.w};
    float mv[4] = {mid.x, mid.y, mid.z, mid.w};
    float rv[4] = {rgt.x, rgt.y, rgt.z, rgt.w};
    float bv[4] = {bb.x, bb.y, bb.z, bb.w};
    float rr[4];
#pragma unroll
    for (int t = 0; t < 4; t++) {
        float z = fmaf(lv[t], wf[3*t], fmaf(mv[t], wf[3*t+1], fmaf(rv[t], wf[3*t+2], bv[t])));
        rr[t] = 0.5f * z * (1.f + erff(z * 0.70710678118654752440f));
    }
    *(float4*)(u + base) = make_float4(rr[0], rr[1], rr[2], rr[3]);
}

// ---------------- TF32 tensor-core GEMM: C = A[MxK] @ W[KxN] (+src) -----------
// CTA tile 128x64x32, 8 warps (4M x 2N), warp tile 32x32 via m16n8k8 frags.
// 3-stage cp.async pipeline. smem: As [3][128][36], Bs [3][32][72].
// DTDEC: epilogue threads owning cols<8 compute dt=softplus(v+bias),
//        dec=exp(dt*-exp(A_log)) and write g_dd.
#define BM 128
#define BN 64
#define BKK 32
#define PADA 36
#define PADB 72
#define NSTG 3
#define GEMM_SMEM (NSTG*(BM*PADA + BKK*PADB) * 4)

template<bool ADD, bool DTDEC>
__global__ void __launch_bounds__(256, 2)
mma_gemm(const float* __restrict__ A, const float* __restrict__ W,
         float* __restrict__ C, const float* __restrict__ add,
         const float* __restrict__ dt_bias, const float* __restrict__ A_log,
         float2* __restrict__ dd,
         int M, int N, int K) {
    extern __shared__ float sm[];
    float* As = sm;                           // [NSTG][BM*PADA]
    float* Bs = sm + NSTG*BM*PADA;            // [NSTG][BKK*PADB]
    const int tid = threadIdx.x;
    const int m0 = blockIdx.y * BM, n0 = blockIdx.x * BN;
    const int warp = tid >> 5, lane = tid & 31;
    const int wm = (warp & 3) * 32, wn = (warp >> 2) * 32;
    const int gr = lane >> 2, tc = lane & 3;

    float c[2][4][4];
#pragma unroll
    for (int i = 0; i < 2; i++)
#pragma unroll
        for (int j = 0; j < 4; j++)
#pragma unroll
            for (int r = 0; r < 4; r++) c[i][j][r] = 0.f;

    auto load_tiles = [&](int k0, int buf) {
        float* as = As + buf * BM * PADA;
        float* bs = Bs + buf * BKK * PADB;
#pragma unroll
        for (int i = 0; i < 4; i++) {                 // A: 128x32 = 1024 float4
            int idx = tid + i * 256;
            int m = idx >> 3, kq = (idx & 7) * 4;
            const float* src = A + (size_t)(m0 + m) * K + k0 + kq;
            asm volatile("cp.async.ca.shared.global [%0], [%1], 16;\n"
                         :: "r"(smem_u32(as + m*PADA + kq)), "l"(src) : "memory");
        }
#pragma unroll
        for (int i = 0; i < 2; i++) {                 // B: 32x64 = 512 float4
            int idx = tid + i * 256;
            int k = idx >> 4, nq = (idx & 15) * 4;
            int col = n0 + nq;
            const float* src = W + (size_t)(k0 + k) * N + col;
            int sz = (col + 3 < N) ? 16 : 0;          // N % 4 == 0 always
            if (sz == 0) src = W;                     // keep pointer valid
            asm volatile("cp.async.ca.shared.global [%0], [%1], 16, %2;\n"
                         :: "r"(smem_u32(bs + k*PADB + nq)), "l"(src), "r"(sz) : "memory");
        }
        asm volatile("cp.async.commit_group;\n" ::: "memory");
    };

    const int nk = K / BKK;
    load_tiles(0, 0);
    if (nk > 1) load_tiles(BKK, 1);
    for (int kt = 0; kt < nk; kt++) {
        int buf = kt % NSTG;
        if (kt + 2 < nk) {
            load_tiles((kt + 2) * BKK, (kt + 2) % NSTG);
            asm volatile("cp.async.wait_group 2;\n" ::: "memory");
        } else if (kt + 1 < nk) {
            asm volatile("cp.async.wait_group 1;\n" ::: "memory");
        } else {
            asm volatile("cp.async.wait_group 0;\n" ::: "memory");
        }
        __syncthreads();
        const float* as = As + buf * BM * PADA;
        const float* bs = Bs + buf * BKK * PADB;
#pragma unroll
        for (int ks = 0; ks < 4; ks++) {
            const int kk = ks * 8;
            unsigned a[2][4], bf[4][2];
#pragma unroll
            for (int i = 0; i < 2; i++) {
                const float* ap = as + (wm + i*16 + gr) * PADA + kk + tc;
                a[i][0] = __float_as_uint(ap[0]);
                a[i][1] = __float_as_uint(ap[8*PADA]);
                a[i][2] = __float_as_uint(ap[4]);
                a[i][3] = __float_as_uint(ap[8*PADA + 4]);
            }
#pragma unroll
            for (int j = 0; j < 4; j++) {
                const float* bp = bs + (kk + tc) * PADB + wn + j*8 + gr;
                bf[j][0] = __float_as_uint(bp[0]);
                bf[j][1] = __float_as_uint(bp[4*PADB]);
            }
#pragma unroll
            for (int i = 0; i < 2; i++)
#pragma unroll
                for (int j = 0; j < 4; j++)
                    asm volatile(
                        "mma.sync.aligned.m16n8k8.row.col.f32.tf32.tf32.f32 "
                        "{%0,%1,%2,%3}, {%4,%5,%6,%7}, {%8,%9}, {%0,%1,%2,%3};"
                        : "+f"(c[i][j][0]), "+f"(c[i][j][1]),
                          "+f"(c[i][j][2]), "+f"(c[i][j][3])
                        : "r"(a[i][0]), "r"(a[i][1]), "r"(a[i][2]), "r"(a[i][3]),
                          "r"(bf[j][0]), "r"(bf[j][1]));
        }
        __syncthreads();
    }

#pragma unroll
    for (int i = 0; i < 2; i++) {
        int mr = m0 + wm + i*16 + gr;
#pragma unroll
        for (int j = 0; j < 4; j++) {
            int col = n0 + wn + j*8 + tc*2;
            if (col < N) {
                size_t o0 = (size_t)mr * N + col;
                size_t o1 = (size_t)(mr + 8) * N + col;
                float v0 = c[i][j][0], v1 = c[i][j][1];
                float v2 = c[i][j][2], v3 = c[i][j][3];
                if (ADD) { v0 += add[o0]; v1 += add[o0+1]; v2 += add[o1]; v3 += add[o1+1]; }
                C[o0] = v0; C[o0+1] = v1; C[o1] = v2; C[o1+1] = v3;
                if (DTDEC && col < 8) {
                    float bias0 = dt_bias[col], bias1 = dt_bias[col+1];
                    float na0 = -expf(A_log[col]), na1 = -expf(A_log[col+1]);
                    float z, dt;
                    z = v0 + bias0; dt = (z > 20.f) ? z : log1pf(expf(z));
                    dd[(size_t)mr*HH + col]       = make_float2(dt, expf(dt*na0));
                    z = v1 + bias1; dt = (z > 20.f) ? z : log1pf(expf(z));
                    dd[(size_t)mr*HH + col+1]     = make_float2(dt, expf(dt*na1));
                    z = v2 + bias0; dt = (z > 20.f) ? z : log1pf(expf(z));
                    dd[(size_t)(mr+8)*HH + col]   = make_float2(dt, expf(dt*na0));
                    z = v3 + bias1; dt = (z > 20.f) ? z : log1pf(expf(z));
                    dd[(size_t)(mr+8)*HH + col+1] = make_float2(dt, expf(dt*na1));
                }
            }
        }
    }
}

// ---------------- selective scan: one CTA per (b,h,n-half), f32x2 packed ------
// 128 CTAs. state (64p x 32n) in regs as f32x2 pairs: thread t -> p=t>>2,
// 8 n (4 pairs). half 0 writes y0 = x*Ds + dot; half 1 writes y1 = dot.
__global__ void scan_kernel(const float* __restrict__ u, const float* __restrict__ dbc,
                            const float2* __restrict__ dd, const float* __restrict__ Ds,
                            float* __restrict__ y0, float* __restrict__ y1) {
    const int bh = blockIdx.x >> 1, half = blockIdx.x & 1;
    const int b = bh >> 3, h = bh & 7;
    const int tid = threadIdx.x;
    const int p = tid >> 2, q = tid & 3, nq = q * 8;

    __shared__ alignas(16) float  us [2][8][64];
    __shared__ alignas(16) float  Bsm[2][8][32];
    __shared__ alignas(16) float  Csm[2][8][32];
    __shared__ alignas(16) float2 dds[2][8];

    const size_t rowbase = (size_t)b * LL;
    unsigned long long st2[4];
#pragma unroll
    for (int i = 0; i < 4; i++) st2[i] = 0ull;
    const float Dh = Ds[h];
    const int nb = HH + half * 32;           // B offset within dbc row
    const int nc = HH + NN + half * 32;      // C offset within dbc row

    auto issue = [&](int chunk, int bi) {
        int l0 = chunk * 8;
        for (int t = tid; t < 264; t += 256) {
            if (t < 128) {                    // u slice: 8 x 64 floats
                int j = t >> 4, f = (t & 15) * 4;
                const float* src = u + (rowbase + l0 + j)*DIN + h*64 + f;
                asm volatile("cp.async.ca.shared.global [%0], [%1], 16;\n"
                             :: "r"(smem_u32(&us[bi][j][f])), "l"(src) : "memory");
            } else if (t < 192) {             // B half: 8 x 32
                int r = t - 128; int j = r >> 3, f = (r & 7) * 4;
                const float* src = dbc + (rowbase + l0 + j)*XPROJ_N + nb + f;
                asm volatile("cp.async.ca.shared.global [%0], [%1], 16;\n"
                             :: "r"(smem_u32(&Bsm[bi][j][f])), "l"(src) : "memory");
            } else if (t < 256) {             // C half: 8 x 32
                int r = t - 192; int j = r >> 3, f = (r & 7) * 4;
                const float* src = dbc + (rowbase + l0 + j)*XPROJ_N + nc + f;
                asm volatile("cp.async.ca.shared.global [%0], [%1], 16;\n"
                             :: "r"(smem_u32(&Csm[bi][j][f])), "l"(src) : "memory");
            } else {                          // dt/decay: 8 x float2
                int j = t - 256;
                const float2* src = dd + (rowbase + l0 + j)*HH + h;
                asm volatile("cp.async.ca.shared.global [%0], [%1], 8;\n"
                             :: "r"(smem_u32(&dds[bi][j])), "l"(src) : "memory");
            }
        }
        asm volatile("cp.async.commit_group;\n" ::: "memory");
    };

    issue(0, 0);
    const int nch = LL / 8;
    for (int cix = 0; cix < nch; cix++) {
        int bi = cix & 1;
        if (cix + 1 < nch) {
            issue(cix + 1, bi ^ 1);
            asm volatile("cp.async.wait_group 1;\n" ::: "memory");
        } else {
            asm volatile("cp.async.wait_group 0;\n" ::: "memory");
        }
        __syncthreads();
#pragma unroll
        for (int j = 0; j < 8; j++) {
            float2 d2 = dds[bi][j];
            float xp  = us[bi][j][p];
            float a   = d2.x * xp;
            unsigned long long a2   = pack2(a, a);
            unsigned long long dec2 = pack2(d2.y, d2.y);
            const ulonglong2* B2 = (const ulonglong2*)&Bsm[bi][j][nq];
            const ulonglong2* C2 = (const ulonglong2*)&Csm[bi][j][nq];
            ulonglong2 b01 = B2[0], b23 = B2[1];
            ulonglong2 c01 = C2[0], c23 = C2[1];
            unsigned long long acc2 = 0ull;
            st2[0] = fma2(st2[0], dec2, mul2(a2, b01.x)); acc2 = fma2(st2[0], c01.x, acc2);
            st2[1] = fma2(st2[1], dec2, mul2(a2, b01.y)); acc2 = fma2(st2[1], c01.y, acc2);
            st2[2] = fma2(st2[2], dec2, mul2(a2, b23.x)); acc2 = fma2(st2[2], c23.x, acc2);
            st2[3] = fma2(st2[3], dec2, mul2(a2, b23.y)); acc2 = fma2(st2[3], c23.y, acc2);
            float acc = pair_sum(acc2);
            acc += __shfl_xor_sync(0xFFFFFFFFu, acc, 1);
            acc += __shfl_xor_sync(0xFFFFFFFFu, acc, 2);
            if (q == 0) {
                size_t o = (rowbase + cix*8 + j)*DIN + h*64 + p;
                if (half == 0) y0[o] = fmaf(xp, Dh, acc);
                else           y1[o] = acc;
            }
        }
        __syncthreads();
    }
}

// ---------------- launch ------------------------------------------------------
extern "C" void kernel_launch(void* const* d_in, const int* in_sizes, int n_in,
                              void* d_out, int out_size) {
    const float* src     = (const float*)d_in[0];
    const float* ln_w    = (const float*)d_in[1];
    const float* ln_b    = (const float*)d_in[2];
    const float* W_in    = (const float*)d_in[3];
    const float* conv_w  = (const float*)d_in[4];
    const float* conv_b  = (const float*)d_in[5];
    const float* W_xproj = (const float*)d_in[6];
    const float* dt_bias = (const float*)d_in[7];
    const float* A_log   = (const float*)d_in[8];
    const float* Ds      = (const float*)d_in[9];
    const float* oln_w   = (const float*)d_in[10];
    const float* oln_b   = (const float*)d_in[11];
    const float* W_out   = (const float*)d_in[12];
    float* out = (float*)d_out;

    float  *p_xln, *p_u0, *p_u, *p_dbc, *p_y0, *p_y1, *p_yln;
    float2 *p_dd;
    cudaGetSymbolAddress((void**)&p_xln, g_xln);
    cudaGetSymbolAddress((void**)&p_u0,  g_u0);
    cudaGetSymbolAddress((void**)&p_u,   g_u);
    cudaGetSymbolAddress((void**)&p_dbc, g_dbc);
    cudaGetSymbolAddress((void**)&p_dd,  g_dd);
    cudaGetSymbolAddress((void**)&p_y0,  g_y0);
    cudaGetSymbolAddress((void**)&p_y1,  g_y1);
    cudaGetSymbolAddress((void**)&p_yln, g_yln);

    cudaFuncSetAttribute(mma_gemm<false,false>, cudaFuncAttributeMaxDynamicSharedMemorySize, GEMM_SMEM);
    cudaFuncSetAttribute(mma_gemm<false,true>,  cudaFuncAttributeMaxDynamicSharedMemorySize, GEMM_SMEM);
    cudaFuncSetAttribute(mma_gemm<true,false>,  cudaFuncAttributeMaxDynamicSharedMemorySize, GEMM_SMEM);

    // 1. input LN
    ln_kernel<DD, false><<<ROWS, 256>>>(src, nullptr, ln_w, ln_b, p_xln);
    // 2. u0 = xln @ W_in  (16384 x 512, K=256)
    mma_gemm<false,false><<<dim3(DIN/BN, ROWS/BM), 256, GEMM_SMEM>>>(
        p_xln, W_in, p_u0, nullptr, nullptr, nullptr, nullptr, ROWS, DIN, DD);
    // 3. depthwise conv3 + GELU (float4)
    conv_gelu_kernel<<<ROWS, DIN/4>>>(p_u0, conv_w, conv_b, p_u);
    // 4. dbc = u @ W_xproj (16384 x 136, K=512), dt/decay fused in epilogue
    mma_gemm<false,true><<<dim3((XPROJ_N + BN - 1)/BN, ROWS/BM), 256, GEMM_SMEM>>>(
        p_u, W_xproj, p_dbc, nullptr, dt_bias, A_log, p_dd, ROWS, XPROJ_N, DIN);
    // 5. selective scan, N split across 2 CTAs per (b,h)
    scan_kernel<<<BB*HH*2, 256>>>(p_u, p_dbc, p_dd, Ds, p_y0, p_y1);
    // 6. output LN over (y0 + y1)
    ln_kernel<DIN, true><<<ROWS, 256>>>(p_y0, p_y1, oln_w, oln_b, p_yln);
    // 7. out = src + yln @ W_out (16384 x 256, K=512)
    mma_gemm<true,false><<<dim3(DD/BN, ROWS/BM), 256, GEMM_SMEM>>>(
        p_yln, W_out, out, src, nullptr, nullptr, nullptr, ROWS, DD, DIN);
}

// round 12
// speedup vs baseline: 2.4003x; 1.0871x over previous
#include <cuda_runtime.h>
#include <cuda_bf16.h>
#include <math.h>

// Problem constants (VSSOnewayLayer): B=8, L=2048, D=256, DIN=512, N=64, P=64, H=8
#define BB 8
#define LL 2048
#define DD 256
#define DIN 512
#define NN 64
#define PP 64
#define HH 8
#define ROWS (BB*LL)          // 16384
#define XPROJ_N (HH + 2*NN)   // 136

// ---------------- scratch (device globals; no allocation allowed) -------------
__device__ float  g_xln[ROWS*DD];
__device__ float  g_u0 [ROWS*DIN];
__device__ float  g_u  [ROWS*DIN];
__device__ float  g_dbc[ROWS*XPROJ_N];
__device__ float2 g_dd [ROWS*HH];
__device__ float  g_y0 [ROWS*DIN];
__device__ float  g_y1 [ROWS*DIN];
__device__ float  g_y2 [ROWS*DIN];
__device__ float  g_y3 [ROWS*DIN];
__device__ float  g_yln[ROWS*DIN];

// ---------------- helpers ----------------------------------------------------
__device__ __forceinline__ unsigned smem_u32(const void* p) {
    return (unsigned)__cvta_generic_to_shared(p);
}
__device__ __forceinline__ unsigned long long pack2(float lo, float hi) {
    unsigned long long r;
    asm("mov.b64 %0, {%1, %2};" : "=l"(r) : "f"(lo), "f"(hi));
    return r;
}
__device__ __forceinline__ unsigned long long mul2(unsigned long long a, unsigned long long b) {
    unsigned long long r;
    asm("mul.rn.f32x2 %0, %1, %2;" : "=l"(r) : "l"(a), "l"(b));
    return r;
}
__device__ __forceinline__ unsigned long long fma2(unsigned long long a, unsigned long long b,
                                                   unsigned long long c) {
    unsigned long long r;
    asm("fma.rn.f32x2 %0, %1, %2, %3;" : "=l"(r) : "l"(a), "l"(b), "l"(c));
    return r;
}
__device__ __forceinline__ float pair_sum(unsigned long long v) {
    float lo, hi;
    asm("mov.b64 {%0, %1}, %2;" : "=f"(lo), "=f"(hi) : "l"(v));
    return lo + hi;
}

// ---------------- LayerNorm (last-dim DN, 256 threads, NS summed inputs) ------
template<int DN, int NS>
__global__ void ln_kernel(const float* __restrict__ x, const float* __restrict__ x2,
                          const float* __restrict__ x3, const float* __restrict__ x4,
                          const float* __restrict__ w, const float* __restrict__ b,
                          float* __restrict__ out) {
    constexpr int E = DN / 256;
    int row = blockIdx.x;
    const float* xr  = x + (size_t)row * DN;
    const float* xr2 = (NS >= 2) ? (x2 + (size_t)row * DN) : nullptr;
    const float* xr3 = (NS >= 4) ? (x3 + (size_t)row * DN) : nullptr;
    const float* xr4 = (NS >= 4) ? (x4 + (size_t)row * DN) : nullptr;
    float v[E];
    float s = 0.f, s2 = 0.f;
#pragma unroll
    for (int e = 0; e < E; e++) {
        int i = threadIdx.x + e*256;
        v[e] = xr[i];
        if (NS >= 2) v[e] += xr2[i];
        if (NS >= 4) v[e] += xr3[i] + xr4[i];
        s  += v[e];
        s2 += v[e]*v[e];
    }
#pragma unroll
    for (int off = 16; off > 0; off >>= 1) {
        s  += __shfl_xor_sync(0xFFFFFFFFu, s,  off);
        s2 += __shfl_xor_sync(0xFFFFFFFFu, s2, off);
    }
    __shared__ float rs[8], rs2[8];
    int wid = threadIdx.x >> 5, lane = threadIdx.x & 31;
    if (lane == 0) { rs[wid] = s; rs2[wid] = s2; }
    __syncthreads();
    __shared__ float mean_s, rstd_s;
    if (threadIdx.x == 0) {
        float S = 0.f, S2 = 0.f;
#pragma unroll
        for (int i = 0; i < 8; i++) { S += rs[i]; S2 += rs2[i]; }
        float m = S / DN;
        float var = S2 / DN - m*m;
        mean_s = m;
        rstd_s = rsqrtf(var + 1e-5f);
    }
    __syncthreads();
    float m = mean_s, r = rstd_s;
    float* orow = out + (size_t)row * DN;
#pragma unroll
    for (int e = 0; e < E; e++) {
        int i = threadIdx.x + e*256;
        orow[i] = (v[e] - m) * r * w[i] + b[i];
    }
}

// ---------------- depthwise conv3 (SAME, zero pad) + exact GELU ---------------
__global__ void conv_gelu_kernel(const float* __restrict__ u0, const float* __restrict__ cw,
                                 const float* __restrict__ cb, float* __restrict__ u) {
    int row = blockIdx.x;          // b*L + l
    int l = row & (LL - 1);
    int c4 = threadIdx.x * 4;
    size_t base = (size_t)row * DIN + c4;
    float4 mid = *(const float4*)(u0 + base);
    float4 lft = (l > 0)      ? *(const float4*)(u0 + base - DIN) : make_float4(0,0,0,0);
    float4 rgt = (l < LL - 1) ? *(const float4*)(u0 + base + DIN) : make_float4(0,0,0,0);
    float4 bb = *(const float4*)(cb + c4);

    float wf[12];
    *(float4*)&wf[0] = *(const float4*)(cw + c4*3);
    *(float4*)&wf[4] = *(const float4*)(cw + c4*3 + 4);
    *(float4*)&wf[8] = *(const float4*)(cw + c4*3 + 8);

    float lv[4] = {lft.x, lft.y, lft.z, lft.w};
    float mv[4] = {mid.x, mid.y, mid.z, mid.w};
    float rv[4] = {rgt.x, rgt.y, rgt.z, rgt.w};
    float bv[4] = {bb.x, bb.y, bb.z, bb.w};
    float rr[4];
#pragma unroll
    for (int t = 0; t < 4; t++) {
        float z = fmaf(lv[t], wf[3*t], fmaf(mv[t], wf[3*t+1], fmaf(rv[t], wf[3*t+2], bv[t])));
        rr[t] = 0.5f * z * (1.f + erff(z * 0.70710678118654752440f));
    }
    *(float4*)(u + base) = make_float4(rr[0], rr[1], rr[2], rr[3]);
}

// ---------------- TF32 tensor-core GEMM: C = A[MxK] @ W[KxN] (+src) -----------
#define BM 128
#define BN 64
#define BKK 32
#define PADA 36
#define PADB 72
#define NSTG 3
#define GEMM_SMEM (NSTG*(BM*PADA + BKK*PADB) * 4)

template<bool ADD, bool DTDEC>
__global__ void __launch_bounds__(256, 2)
mma_gemm(const float* __restrict__ A, const float* __restrict__ W,
         float* __restrict__ C, const float* __restrict__ add,
         const float* __restrict__ dt_bias, const float* __restrict__ A_log,
         float2* __restrict__ dd,
         int M, int N, int K) {
    extern __shared__ float sm[];
    float* As = sm;                           // [NSTG][BM*PADA]
    float* Bs = sm + NSTG*BM*PADA;            // [NSTG][BKK*PADB]
    const int tid = threadIdx.x;
    const int m0 = blockIdx.y * BM, n0 = blockIdx.x * BN;
    const int warp = tid >> 5, lane = tid & 31;
    const int wm = (warp & 3) * 32, wn = (warp >> 2) * 32;
    const int gr = lane >> 2, tc = lane & 3;

    float c[2][4][4];
#pragma unroll
    for (int i = 0; i < 2; i++)
#pragma unroll
        for (int j = 0; j < 4; j++)
#pragma unroll
            for (int r = 0; r < 4; r++) c[i][j][r] = 0.f;

    auto load_tiles = [&](int k0, int buf) {
        float* as = As + buf * BM * PADA;
        float* bs = Bs + buf * BKK * PADB;
#pragma unroll
        for (int i = 0; i < 4; i++) {                 // A: 128x32 = 1024 float4
            int idx = tid + i * 256;
            int m = idx >> 3, kq = (idx & 7) * 4;
            const float* src = A + (size_t)(m0 + m) * K + k0 + kq;
            asm volatile("cp.async.ca.shared.global [%0], [%1], 16;\n"
                         :: "r"(smem_u32(as + m*PADA + kq)), "l"(src) : "memory");
        }
#pragma unroll
        for (int i = 0; i < 2; i++) {                 // B: 32x64 = 512 float4
            int idx = tid + i * 256;
            int k = idx >> 4, nq = (idx & 15) * 4;
            int col = n0 + nq;
            const float* src = W + (size_t)(k0 + k) * N + col;
            int sz = (col + 3 < N) ? 16 : 0;          // N % 4 == 0 always
            if (sz == 0) src = W;                     // keep pointer valid
            asm volatile("cp.async.ca.shared.global [%0], [%1], 16, %2;\n"
                         :: "r"(smem_u32(bs + k*PADB + nq)), "l"(src), "r"(sz) : "memory");
        }
        asm volatile("cp.async.commit_group;\n" ::: "memory");
    };

    const int nk = K / BKK;
    load_tiles(0, 0);
    if (nk > 1) load_tiles(BKK, 1);
    for (int kt = 0; kt < nk; kt++) {
        int buf = kt % NSTG;
        if (kt + 2 < nk) {
            load_tiles((kt + 2) * BKK, (kt + 2) % NSTG);
            asm volatile("cp.async.wait_group 2;\n" ::: "memory");
        } else if (kt + 1 < nk) {
            asm volatile("cp.async.wait_group 1;\n" ::: "memory");
        } else {
            asm volatile("cp.async.wait_group 0;\n" ::: "memory");
        }
        __syncthreads();
        const float* as = As + buf * BM * PADA;
        const float* bs = Bs + buf * BKK * PADB;
#pragma unroll
        for (int ks = 0; ks < 4; ks++) {
            const int kk = ks * 8;
            unsigned a[2][4], bf[4][2];
#pragma unroll
            for (int i = 0; i < 2; i++) {
                const float* ap = as + (wm + i*16 + gr) * PADA + kk + tc;
                a[i][0] = __float_as_uint(ap[0]);
                a[i][1] = __float_as_uint(ap[8*PADA]);
                a[i][2] = __float_as_uint(ap[4]);
                a[i][3] = __float_as_uint(ap[8*PADA + 4]);
            }
#pragma unroll
            for (int j = 0; j < 4; j++) {
                const float* bp = bs + (kk + tc) * PADB + wn + j*8 + gr;
                bf[j][0] = __float_as_uint(bp[0]);
                bf[j][1] = __float_as_uint(bp[4*PADB]);
            }
#pragma unroll
            for (int i = 0; i < 2; i++)
#pragma unroll
                for (int j = 0; j < 4; j++)
                    asm volatile(
                        "mma.sync.aligned.m16n8k8.row.col.f32.tf32.tf32.f32 "
                        "{%0,%1,%2,%3}, {%4,%5,%6,%7}, {%8,%9}, {%0,%1,%2,%3};"
                        : "+f"(c[i][j][0]), "+f"(c[i][j][1]),
                          "+f"(c[i][j][2]), "+f"(c[i][j][3])
                        : "r"(a[i][0]), "r"(a[i][1]), "r"(a[i][2]), "r"(a[i][3]),
                          "r"(bf[j][0]), "r"(bf[j][1]));
        }
        __syncthreads();
    }

#pragma unroll
    for (int i = 0; i < 2; i++) {
        int mr = m0 + wm + i*16 + gr;
#pragma unroll
        for (int j = 0; j < 4; j++) {
            int col = n0 + wn + j*8 + tc*2;
            if (col < N) {
                size_t o0 = (size_t)mr * N + col;
                size_t o1 = (size_t)(mr + 8) * N + col;
                float v0 = c[i][j][0], v1 = c[i][j][1];
                float v2 = c[i][j][2], v3 = c[i][j][3];
                if (ADD) { v0 += add[o0]; v1 += add[o0+1]; v2 += add[o1]; v3 += add[o1+1]; }
                C[o0] = v0; C[o0+1] = v1; C[o1] = v2; C[o1+1] = v3;
                if (DTDEC && col < 8) {
                    float bias0 = dt_bias[col], bias1 = dt_bias[col+1];
                    float na0 = -expf(A_log[col]), na1 = -expf(A_log[col+1]);
                    float z, dt;
                    z = v0 + bias0; dt = (z > 20.f) ? z : log1pf(expf(z));
                    dd[(size_t)mr*HH + col]       = make_float2(dt, expf(dt*na0));
                    z = v1 + bias1; dt = (z > 20.f) ? z : log1pf(expf(z));
                    dd[(size_t)mr*HH + col+1]     = make_float2(dt, expf(dt*na1));
                    z = v2 + bias0; dt = (z > 20.f) ? z : log1pf(expf(z));
                    dd[(size_t)(mr+8)*HH + col]   = make_float2(dt, expf(dt*na0));
                    z = v3 + bias1; dt = (z > 20.f) ? z : log1pf(expf(z));
                    dd[(size_t)(mr+8)*HH + col+1] = make_float2(dt, expf(dt*na1));
                }
            }
        }
    }
}

// ---------------- selective scan: one CTA per (b,h,n-quarter) -----------------
// 256 CTAs (all resident; ~16 warps/SM on most SMs). Thread t -> p = t>>2,
// q = t&3 owning n locals [q*4, q*4+4) of this CTA's 16-wide n-quarter.
// 16-step chunks, 3-buffer cp.async ring, ONE __syncthreads per chunk:
//   iter c: wait(c done); sync; issue(c+2 -> (c+2)%3); compute(c%3).
//   Safe: buffer (c+2)%3 == (c-1)%3 was last read in chunk c-1, which the
//   barrier at iter c has fully retired for all warps.
#define SCHUNK 16
__global__ void __launch_bounds__(256, 2)
scan_kernel(const float* __restrict__ u, const float* __restrict__ dbc,
            const float2* __restrict__ dd, const float* __restrict__ Ds,
            float* __restrict__ y0, float* __restrict__ y1,
            float* __restrict__ y2, float* __restrict__ y3) {
    const int bh = blockIdx.x >> 2, quarter = blockIdx.x & 3;
    const int b = bh >> 3, h = bh & 7;
    const int tid = threadIdx.x;
    const int p = tid >> 2, q = tid & 3;

    __shared__ alignas(16) float  us [3][SCHUNK][64];
    __shared__ alignas(16) float  Bq [3][SCHUNK][16];
    __shared__ alignas(16) float  Cq [3][SCHUNK][16];
    __shared__ alignas(16) float2 dds[3][SCHUNK];

    float* yq = (quarter == 0) ? y0 : (quarter == 1) ? y1 : (quarter == 2) ? y2 : y3;
    const size_t rowbase = (size_t)b * LL;
    const int nb = HH + quarter * 16;            // B slice offset within dbc row
    const int nc = HH + NN + quarter * 16;       // C slice offset within dbc row
    const float Dh = Ds[h];

    unsigned long long st2[2] = {0ull, 0ull};

    auto issue = [&](int chunk, int bi) {
        int l0 = chunk * SCHUNK;
        for (int t = tid; t < 400; t += 256) {
            if (t < 256) {                        // u slice: 16 rows x 64 floats
                int j = t >> 4, f = (t & 15) * 4;
                const float* src = u + (rowbase + l0 + j)*DIN + h*64 + f;
                asm volatile("cp.async.ca.shared.global [%0], [%1], 16;\n"
                             :: "r"(smem_u32(&us[bi][j][f])), "l"(src) : "memory");
            } else if (t < 320) {                 // B quarter: 16 x 16
                int r = t - 256; int j = r >> 2, f = (r & 3) * 4;
                const float* src = dbc + (rowbase + l0 + j)*XPROJ_N + nb + f;
                asm volatile("cp.async.ca.shared.global [%0], [%1], 16;\n"
                             :: "r"(smem_u32(&Bq[bi][j][f])), "l"(src) : "memory");
            } else if (t < 384) {                 // C quarter: 16 x 16
                int r = t - 320; int j = r >> 2, f = (r & 3) * 4;
                const float* src = dbc + (rowbase + l0 + j)*XPROJ_N + nc + f;
                asm volatile("cp.async.ca.shared.global [%0], [%1], 16;\n"
                             :: "r"(smem_u32(&Cq[bi][j][f])), "l"(src) : "memory");
            } else {                              // dt/decay: 16 x float2
                int j = t - 384;
                const float2* src = dd + (rowbase + l0 + j)*HH + h;
                asm volatile("cp.async.ca.shared.global [%0], [%1], 8;\n"
                             :: "r"(smem_u32(&dds[bi][j])), "l"(src) : "memory");
            }
        }
        asm volatile("cp.async.commit_group;\n" ::: "memory");
    };

    const int nch = LL / SCHUNK;                  // 128
    issue(0, 0);
    issue(1, 1);
    for (int c = 0; c < nch; c++) {
        if (c == nch - 1) { asm volatile("cp.async.wait_group 0;\n" ::: "memory"); }
        else              { asm volatile("cp.async.wait_group 1;\n" ::: "memory"); }
        __syncthreads();
        int bi = c % 3;
        if (c + 2 < nch) issue(c + 2, (c + 2) % 3);
#pragma unroll
        for (int j = 0; j < SCHUNK; j++) {
            float2 d2 = dds[bi][j];
            float xp  = us[bi][j][p];
            float a   = d2.x * xp;
            unsigned long long a2   = pack2(a, a);
            unsigned long long dec2 = pack2(d2.y, d2.y);
            ulonglong2 bq = *(const ulonglong2*)&Bq[bi][j][q*4];
            ulonglong2 cq = *(const ulonglong2*)&Cq[bi][j][q*4];
            st2[0] = fma2(st2[0], dec2, mul2(a2, bq.x));
            unsigned long long acc2 = mul2(st2[0], cq.x);
            st2[1] = fma2(st2[1], dec2, mul2(a2, bq.y));
            acc2 = fma2(st2[1], cq.y, acc2);
            float acc = pair_sum(acc2);
            acc += __shfl_xor_sync(0xFFFFFFFFu, acc, 1);
            acc += __shfl_xor_sync(0xFFFFFFFFu, acc, 2);
            if (q == 0) {
                size_t o = (rowbase + c*SCHUNK + j)*DIN + h*64 + p;
                yq[o] = (quarter == 0) ? fmaf(xp, Dh, acc) : acc;
            }
        }
    }
}

// ---------------- launch ------------------------------------------------------
extern "C" void kernel_launch(void* const* d_in, const int* in_sizes, int n_in,
                              void* d_out, int out_size) {
    const float* src     = (const float*)d_in[0];
    const float* ln_w    = (const float*)d_in[1];
    const float* ln_b    = (const float*)d_in[2];
    const float* W_in    = (const float*)d_in[3];
    const float* conv_w  = (const float*)d_in[4];
    const float* conv_b  = (const float*)d_in[5];
    const float* W_xproj = (const float*)d_in[6];
    const float* dt_bias = (const float*)d_in[7];
    const float* A_log   = (const float*)d_in[8];
    const float* Ds      = (const float*)d_in[9];
    const float* oln_w   = (const float*)d_in[10];
    const float* oln_b   = (const float*)d_in[11];
    const float* W_out   = (const float*)d_in[12];
    float* out = (float*)d_out;

    float  *p_xln, *p_u0, *p_u, *p_dbc, *p_y0, *p_y1, *p_y2, *p_y3, *p_yln;
    float2 *p_dd;
    cudaGetSymbolAddress((void**)&p_xln, g_xln);
    cudaGetSymbolAddress((void**)&p_u0,  g_u0);
    cudaGetSymbolAddress((void**)&p_u,   g_u);
    cudaGetSymbolAddress((void**)&p_dbc, g_dbc);
    cudaGetSymbolAddress((void**)&p_dd,  g_dd);
    cudaGetSymbolAddress((void**)&p_y0,  g_y0);
    cudaGetSymbolAddress((void**)&p_y1,  g_y1);
    cudaGetSymbolAddress((void**)&p_y2,  g_y2);
    cudaGetSymbolAddress((void**)&p_y3,  g_y3);
    cudaGetSymbolAddress((void**)&p_yln, g_yln);

    cudaFuncSetAttribute(mma_gemm<false,false>, cudaFuncAttributeMaxDynamicSharedMemorySize, GEMM_SMEM);
    cudaFuncSetAttribute(mma_gemm<false,true>,  cudaFuncAttributeMaxDynamicSharedMemorySize, GEMM_SMEM);
    cudaFuncSetAttribute(mma_gemm<true,false>,  cudaFuncAttributeMaxDynamicSharedMemorySize, GEMM_SMEM);

    // 1. input LN
    ln_kernel<DD, 1><<<ROWS, 256>>>(src, nullptr, nullptr, nullptr, ln_w, ln_b, p_xln);
    // 2. u0 = xln @ W_in  (16384 x 512, K=256)
    mma_gemm<false,false><<<dim3(DIN/BN, ROWS/BM), 256, GEMM_SMEM>>>(
        p_xln, W_in, p_u0, nullptr, nullptr, nullptr, nullptr, ROWS, DIN, DD);
    // 3. depthwise conv3 + GELU (float4)
    conv_gelu_kernel<<<ROWS, DIN/4>>>(p_u0, conv_w, conv_b, p_u);
    // 4. dbc = u @ W_xproj (16384 x 136, K=512), dt/decay fused in epilogue
    mma_gemm<false,true><<<dim3((XPROJ_N + BN - 1)/BN, ROWS/BM), 256, GEMM_SMEM>>>(
        p_u, W_xproj, p_dbc, nullptr, dt_bias, A_log, p_dd, ROWS, XPROJ_N, DIN);
    // 5. selective scan, N split across 4 CTAs per (b,h)
    scan_kernel<<<BB*HH*4, 256>>>(p_u, p_dbc, p_dd, Ds, p_y0, p_y1, p_y2, p_y3);
    // 6. output LN over (y0 + y1 + y2 + y3)
    ln_kernel<DIN, 4><<<ROWS, 256>>>(p_y0, p_y1, p_y2, p_y3, oln_w, oln_b, p_yln);
    // 7. out = src + yln @ W_out (16384 x 256, K=512)
    mma_gemm<true,false><<<dim3(DD/BN, ROWS/BM), 256, GEMM_SMEM>>>(
        p_yln, W_out, out, src, nullptr, nullptr, nullptr, ROWS, DD, DIN);
}

// round 15
// speedup vs baseline: 3.1232x; 1.3011x over previous
#include <cuda_runtime.h>
#include <cuda_bf16.h>
#include <math.h>

// Problem constants (VSSOnewayLayer): B=8, L=2048, D=256, DIN=512, N=64, P=64, H=8
#define BB 8
#define LL 2048
#define DD 256
#define DIN 512
#define NN 64
#define PP 64
#define HH 8
#define ROWS (BB*LL)          // 16384
#define XPROJ_N (HH + 2*NN)   // 136
#define TBLK 64               // SSD block length
#define NBLK (LL/TBLK)        // 32 blocks per (b,h)
#define NBHK (BB*HH*NBLK)     // 2048 total blocks
#define T64 68                // padded smem row (68*4 B, 16B-aligned rows)

// ---------------- scratch (device globals; no allocation allowed) -------------
__device__ float  g_xln[ROWS*DD];
__device__ float  g_u0 [ROWS*DIN];
__device__ float  g_u  [ROWS*DIN];
__device__ float  g_dbc[ROWS*XPROJ_N];
__device__ float2 g_dd [ROWS*HH];
__device__ float  g_y  [ROWS*DIN];
__device__ float  g_yln[ROWS*DIN];
__device__ float  g_S  [NBHK*PP*NN];   // per-block state contribution
__device__ float  g_hst[NBHK*PP*NN];   // per-block incoming state
__device__ float  g_cdT[NBHK];         // per-block dt-sum

// ---------------- helpers ----------------------------------------------------
__device__ __forceinline__ unsigned smem_u32(const void* p) {
    return (unsigned)__cvta_generic_to_shared(p);
}
__device__ __forceinline__ unsigned long long pack2(float lo, float hi) {
    unsigned long long r;
    asm("mov.b64 %0, {%1, %2};" : "=l"(r) : "f"(lo), "f"(hi));
    return r;
}
__device__ __forceinline__ unsigned long long fma2(unsigned long long a, unsigned long long b,
                                                   unsigned long long c) {
    unsigned long long r;
    asm("fma.rn.f32x2 %0, %1, %2, %3;" : "=l"(r) : "l"(a), "l"(b), "l"(c));
    return r;
}
__device__ __forceinline__ float2 unpk(unsigned long long v) {
    float lo, hi;
    asm("mov.b64 {%0, %1}, %2;" : "=f"(lo), "=f"(hi) : "l"(v));
    return make_float2(lo, hi);
}

// ---------------- LayerNorm (last-dim DN, 256 threads) ------------------------
template<int DN>
__global__ void ln_kernel(const float* __restrict__ x, const float* __restrict__ w,
                          const float* __restrict__ b, float* __restrict__ out) {
    constexpr int E = DN / 256;
    int row = blockIdx.x;
    const float* xr = x + (size_t)row * DN;
    float v[E];
    float s = 0.f, s2 = 0.f;
#pragma unroll
    for (int e = 0; e < E; e++) {
        v[e] = xr[threadIdx.x + e*256];
        s  += v[e];
        s2 += v[e]*v[e];
    }
#pragma unroll
    for (int off = 16; off > 0; off >>= 1) {
        s  += __shfl_xor_sync(0xFFFFFFFFu, s,  off);
        s2 += __shfl_xor_sync(0xFFFFFFFFu, s2, off);
    }
    __shared__ float rs[8], rs2[8];
    int wid = threadIdx.x >> 5, lane = threadIdx.x & 31;
    if (lane == 0) { rs[wid] = s; rs2[wid] = s2; }
    __syncthreads();
    __shared__ float mean_s, rstd_s;
    if (threadIdx.x == 0) {
        float S = 0.f, S2 = 0.f;
#pragma unroll
        for (int i = 0; i < 8; i++) { S += rs[i]; S2 += rs2[i]; }
        float m = S / DN;
        float var = S2 / DN - m*m;
        mean_s = m;
        rstd_s = rsqrtf(var + 1e-5f);
    }
    __syncthreads();
    float m = mean_s, r = rstd_s;
    float* orow = out + (size_t)row * DN;
#pragma unroll
    for (int e = 0; e < E; e++) {
        int i = threadIdx.x + e*256;
        orow[i] = (v[e] - m) * r * w[i] + b[i];
    }
}

// ---------------- depthwise conv3 (SAME, zero pad) + exact GELU ---------------
__global__ void conv_gelu_kernel(const float* __restrict__ u0, const float* __restrict__ cw,
                                 const float* __restrict__ cb, float* __restrict__ u) {
    int row = blockIdx.x;          // b*L + l
    int l = row & (LL - 1);
    int c4 = threadIdx.x * 4;
    size_t base = (size_t)row * DIN + c4;
    float4 mid = *(const float4*)(u0 + base);
    float4 lft = (l > 0)      ? *(const float4*)(u0 + base - DIN) : make_float4(0,0,0,0);
    float4 rgt = (l < LL - 1) ? *(const float4*)(u0 + base + DIN) : make_float4(0,0,0,0);
    float4 bb = *(const float4*)(cb + c4);

    float wf[12];
    *(float4*)&wf[0] = *(const float4*)(cw + c4*3);
    *(float4*)&wf[4] = *(const float4*)(cw + c4*3 + 4);
    *(float4*)&wf[8] = *(const float4*)(cw + c4*3 + 8);

    float lv[4] = {lft.x, lft.y, lft.z, lft.w};
    float mv[4] = {mid.x, mid.y, mid.z, mid.w};
    float rv[4] = {rgt.x, rgt.y, rgt.z, rgt.w};
    float bv[4] = {bb.x, bb.y, bb.z, bb.w};
    float rr[4];
#pragma unroll
    for (int t = 0; t < 4; t++) {
        float z = fmaf(lv[t], wf[3*t], fmaf(mv[t], wf[3*t+1], fmaf(rv[t], wf[3*t+2], bv[t])));
        rr[t] = 0.5f * z * (1.f + erff(z * 0.70710678118654752440f));
    }
    *(float4*)(u + base) = make_float4(rr[0], rr[1], rr[2], rr[3]);
}

// ---------------- TF32 tensor-core GEMM: C = A[MxK] @ W[KxN] (+src) -----------
#define BM 128
#define BN 64
#define BKK 32
#define PADA 36
#define PADB 72
#define NSTG 3
#define GEMM_SMEM (NSTG*(BM*PADA + BKK*PADB) * 4)

template<bool ADD, bool DTDEC>
__global__ void __launch_bounds__(256, 2)
mma_gemm(const float* __restrict__ A, const float* __restrict__ W,
         float* __restrict__ C, const float* __restrict__ add,
         const float* __restrict__ dt_bias, const float* __restrict__ A_log,
         float2* __restrict__ dd,
         int M, int N, int K) {
    extern __shared__ float sm[];
    float* As = sm;                           // [NSTG][BM*PADA]
    float* Bs = sm + NSTG*BM*PADA;            // [NSTG][BKK*PADB]
    const int tid = threadIdx.x;
    const int m0 = blockIdx.y * BM, n0 = blockIdx.x * BN;
    const int warp = tid >> 5, lane = tid & 31;
    const int wm = (warp & 3) * 32, wn = (warp >> 2) * 32;
    const int gr = lane >> 2, tc = lane & 3;

    float c[2][4][4];
#pragma unroll
    for (int i = 0; i < 2; i++)
#pragma unroll
        for (int j = 0; j < 4; j++)
#pragma unroll
            for (int r = 0; r < 4; r++) c[i][j][r] = 0.f;

    auto load_tiles = [&](int k0, int buf) {
        float* as = As + buf * BM * PADA;
        float* bs = Bs + buf * BKK * PADB;
#pragma unroll
        for (int i = 0; i < 4; i++) {                 // A: 128x32 = 1024 float4
            int idx = tid + i * 256;
            int m = idx >> 3, kq = (idx & 7) * 4;
            const float* src = A + (size_t)(m0 + m) * K + k0 + kq;
            asm volatile("cp.async.ca.shared.global [%0], [%1], 16;\n"
                         :: "r"(smem_u32(as + m*PADA + kq)), "l"(src) : "memory");
        }
#pragma unroll
        for (int i = 0; i < 2; i++) {                 // B: 32x64 = 512 float4
            int idx = tid + i * 256;
            int k = idx >> 4, nq = (idx & 15) * 4;
            int col = n0 + nq;
            const float* src = W + (size_t)(k0 + k) * N + col;
            int sz = (col + 3 < N) ? 16 : 0;          // N % 4 == 0 always
            if (sz == 0) src = W;                     // keep pointer valid
            asm volatile("cp.async.ca.shared.global [%0], [%1], 16, %2;\n"
                         :: "r"(smem_u32(bs + k*PADB + nq)), "l"(src), "r"(sz) : "memory");
        }
        asm volatile("cp.async.commit_group;\n" ::: "memory");
    };

    const int nk = K / BKK;
    load_tiles(0, 0);
    if (nk > 1) load_tiles(BKK, 1);
    for (int kt = 0; kt < nk; kt++) {
        int buf = kt % NSTG;
        if (kt + 2 < nk) {
            load_tiles((kt + 2) * BKK, (kt + 2) % NSTG);
            asm volatile("cp.async.wait_group 2;\n" ::: "memory");
        } else if (kt + 1 < nk) {
            asm volatile("cp.async.wait_group 1;\n" ::: "memory");
        } else {
            asm volatile("cp.async.wait_group 0;\n" ::: "memory");
        }
        __syncthreads();
        const float* as = As + buf * BM * PADA;
        const float* bs = Bs + buf * BKK * PADB;
#pragma unroll
        for (int ks = 0; ks < 4; ks++) {
            const int kk = ks * 8;
            unsigned a[2][4], bf[4][2];
#pragma unroll
            for (int i = 0; i < 2; i++) {
                const float* ap = as + (wm + i*16 + gr) * PADA + kk + tc;
                a[i][0] = __float_as_uint(ap[0]);
                a[i][1] = __float_as_uint(ap[8*PADA]);
                a[i][2] = __float_as_uint(ap[4]);
                a[i][3] = __float_as_uint(ap[8*PADA + 4]);
            }
#pragma unroll
            for (int j = 0; j < 4; j++) {
                const float* bp = bs + (kk + tc) * PADB + wn + j*8 + gr;
                bf[j][0] = __float_as_uint(bp[0]);
                bf[j][1] = __float_as_uint(bp[4*PADB]);
            }
#pragma unroll
            for (int i = 0; i < 2; i++)
#pragma unroll
                for (int j = 0; j < 4; j++)
                    asm volatile(
                        "mma.sync.aligned.m16n8k8.row.col.f32.tf32.tf32.f32 "
                        "{%0,%1,%2,%3}, {%4,%5,%6,%7}, {%8,%9}, {%0,%1,%2,%3};"
                        : "+f"(c[i][j][0]), "+f"(c[i][j][1]),
                          "+f"(c[i][j][2]), "+f"(c[i][j][3])
                        : "r"(a[i][0]), "r"(a[i][1]), "r"(a[i][2]), "r"(a[i][3]),
                          "r"(bf[j][0]), "r"(bf[j][1]));
        }
        __syncthreads();
    }

#pragma unroll
    for (int i = 0; i < 2; i++) {
        int mr = m0 + wm + i*16 + gr;
#pragma unroll
        for (int j = 0; j < 4; j++) {
            int col = n0 + wn + j*8 + tc*2;
            if (col < N) {
                size_t o0 = (size_t)mr * N + col;
                size_t o1 = (size_t)(mr + 8) * N + col;
                float v0 = c[i][j][0], v1 = c[i][j][1];
                float v2 = c[i][j][2], v3 = c[i][j][3];
                if (ADD) { v0 += add[o0]; v1 += add[o0+1]; v2 += add[o1]; v3 += add[o1+1]; }
                C[o0] = v0; C[o0+1] = v1; C[o1] = v2; C[o1+1] = v3;
                if (DTDEC && col < 8) {
                    float bias0 = dt_bias[col], bias1 = dt_bias[col+1];
                    float na0 = -expf(A_log[col]), na1 = -expf(A_log[col+1]);
                    float z, dt;
                    z = v0 + bias0; dt = (z > 20.f) ? z : log1pf(expf(z));
                    dd[(size_t)mr*HH + col]       = make_float2(dt, expf(dt*na0));
                    z = v1 + bias1; dt = (z > 20.f) ? z : log1pf(expf(z));
                    dd[(size_t)mr*HH + col+1]     = make_float2(dt, expf(dt*na1));
                    z = v2 + bias0; dt = (z > 20.f) ? z : log1pf(expf(z));
                    dd[(size_t)(mr+8)*HH + col]   = make_float2(dt, expf(dt*na0));
                    z = v3 + bias1; dt = (z > 20.f) ? z : log1pf(expf(z));
                    dd[(size_t)(mr+8)*HH + col+1] = make_float2(dt, expf(dt*na1));
                }
            }
        }
    }
}

// ---------------- SSD kernel 1: per-block state contribution S ----------------
// grid NBHK. S[p][n] = sum_s dt_s*exp(A*(cdT-cd_s)) * x_s[p] * B_s[n].
__global__ void __launch_bounds__(256)
ssd_prep(const float* __restrict__ u, const float* __restrict__ dbc,
         const float2* __restrict__ dd, const float* __restrict__ A_log,
         float* __restrict__ S, float* __restrict__ cdT_out) {
    const int blk = blockIdx.x;
    const int bh = blk >> 5, k = blk & (NBLK - 1);
    const int b = bh >> 3, h = bh & 7;
    const int row0 = b * LL + k * TBLK;
    const int tid = threadIdx.x, lane = tid & 31;

    __shared__ float xs[64][T64];     // scaled: coef_s * x_s[p]
    __shared__ float Bsm[64][T64];
    __shared__ float sm_cd[64], sm_dt[64], sm_aux[1];

    // dt inclusive cumsum (threads 0..63 = warps 0,1)
    float dtv = 0.f, v = 0.f;
    if (tid < 64) {
        dtv = dd[(size_t)(row0 + tid) * HH + h].x;
        v = dtv;
#pragma unroll
        for (int off = 1; off < 32; off <<= 1) {
            float o = __shfl_up_sync(0xFFFFFFFFu, v, off);
            if (lane >= off) v += o;
        }
    }
    if (tid == 31) sm_aux[0] = v;
    __syncthreads();
    if (tid >= 32 && tid < 64) v += sm_aux[0];
    if (tid < 64) { sm_cd[tid] = v; sm_dt[tid] = dtv; }
    __syncthreads();

    const float A = -expf(A_log[h]);
    const float cdT = sm_cd[63];
    if (tid == 0) cdT_out[blk] = cdT;

    {   // load x (scaled) and B
        int s = tid >> 2, f0 = (tid & 3) * 16;
        float coef = sm_dt[s] * expf(A * (cdT - sm_cd[s]));
        const float* xsrc = u   + (size_t)(row0 + s) * DIN + h * 64 + f0;
        const float* bsrc = dbc + (size_t)(row0 + s) * XPROJ_N + HH + f0;
#pragma unroll
        for (int i = 0; i < 4; i++) {
            float4 xv = *(const float4*)(xsrc + i * 4);
            xv.x *= coef; xv.y *= coef; xv.z *= coef; xv.w *= coef;
            *(float4*)&xs[s][f0 + i * 4] = xv;
            *(float4*)&Bsm[s][f0 + i * 4] = *(const float4*)(bsrc + i * 4);
        }
    }
    __syncthreads();

    // S[p][n], 16x16 thread grid, 4x4 tile (f32x2 along n)
    const int p0 = (tid >> 4) * 4, n0 = (tid & 15) * 4;
    unsigned long long acc[4][2] = {};
#pragma unroll 8
    for (int s = 0; s < 64; s++) {
        float4 av = *(const float4*)&xs[s][p0];
        ulonglong2 bv = *(const ulonglong2*)&Bsm[s][n0];
        float af[4] = {av.x, av.y, av.z, av.w};
#pragma unroll
        for (int i = 0; i < 4; i++) {
            unsigned long long a2 = pack2(af[i], af[i]);
            acc[i][0] = fma2(a2, bv.x, acc[i][0]);
            acc[i][1] = fma2(a2, bv.y, acc[i][1]);
        }
    }
    float* dst = S + (size_t)blk * (PP * NN);
#pragma unroll
    for (int i = 0; i < 4; i++) {
        ulonglong2 o; o.x = acc[i][0]; o.y = acc[i][1];
        *(ulonglong2*)&dst[(p0 + i) * NN + n0] = o;
    }
}

// ---------------- SSD kernel 2: sequential state carry (64 CTAs) --------------
// h_start[blk] = h; h = exp(A*cdT[blk])*h + S[blk], over k = 0..31.
__global__ void __launch_bounds__(256)
ssd_state(const float* __restrict__ S, const float* __restrict__ cdT,
          const float* __restrict__ A_log, float* __restrict__ hst) {
    const int bh = blockIdx.x, h = bh & 7;
    const float A = -expf(A_log[h]);
    const int off = threadIdx.x * 16;
    float4 hv[4] = {make_float4(0,0,0,0), make_float4(0,0,0,0),
                    make_float4(0,0,0,0), make_float4(0,0,0,0)};
    for (int k = 0; k < NBLK; k++) {
        int blk = bh * NBLK + k;
        float* hd = hst + (size_t)blk * (PP * NN) + off;
        const float* sv = S + (size_t)blk * (PP * NN) + off;
        float G = expf(A * cdT[blk]);
#pragma unroll
        for (int i = 0; i < 4; i++) {
            *(float4*)(hd + i * 4) = hv[i];
            float4 s4 = *(const float4*)(sv + i * 4);
            hv[i].x = fmaf(hv[i].x, G, s4.x);
            hv[i].y = fmaf(hv[i].y, G, s4.y);
            hv[i].z = fmaf(hv[i].z, G, s4.z);
            hv[i].w = fmaf(hv[i].w, G, s4.w);
        }
    }
}

// ---------------- SSD kernel 3: per-block output --------------------------------
// y_t[p] = sum_{s<=t} (C_t.B_s)*exp(A(cd_t-cd_s))*dt_s*x_s[p]
//        + exp(A*cd_t)*(C_t . hst[p][:]) + Ds*x_t[p]
#define SSD3_SMEM (5*64*T64*4 + 64*4*2 + 16)
__global__ void __launch_bounds__(256)
ssd_out(const float* __restrict__ u, const float* __restrict__ dbc,
        const float2* __restrict__ dd, const float* __restrict__ A_log,
        const float* __restrict__ Ds, const float* __restrict__ hst,
        float* __restrict__ y) {
    extern __shared__ float sm3[];
    float* Cs  = sm3;                 // [n][t]
    float* Bsm = Cs  + 64 * T64;      // [n][s]
    float* xs  = Bsm + 64 * T64;      // [s][p] (raw)
    float* hT  = xs  + 64 * T64;      // [n][p]
    float* Ms  = hT  + 64 * T64;      // [s][t] (dt folded, masked)
    float* sm_cd = Ms + 64 * T64;
    float* sm_dt = sm_cd + 64;
    float* sm_aux = sm_dt + 64;

    const int blk = blockIdx.x;
    const int bh = blk >> 5, k = blk & (NBLK - 1);
    const int b = bh >> 3, h = bh & 7;
    const int row0 = b * LL + k * TBLK;
    const int tid = threadIdx.x, lane = tid & 31;

    float dtv = 0.f, v = 0.f;
    if (tid < 64) {
        dtv = dd[(size_t)(row0 + tid) * HH + h].x;
        v = dtv;
#pragma unroll
        for (int off = 1; off < 32; off <<= 1) {
            float o = __shfl_up_sync(0xFFFFFFFFu, v, off);
            if (lane >= off) v += o;
        }
    }
    if (tid == 31) sm_aux[0] = v;
    __syncthreads();
    if (tid >= 32 && tid < 64) v += sm_aux[0];
    if (tid < 64) { sm_cd[tid] = v; sm_dt[tid] = dtv; }

    const float A = -expf(A_log[h]);

    {   // loads: C,B,hst transposed; x natural
        int r = tid >> 2, f0 = (tid & 3) * 16;
        const float* bsrc = dbc + (size_t)(row0 + r) * XPROJ_N + HH;
        const float* csrc = bsrc + NN;
        const float* hsrc = hst + (size_t)blk * (PP * NN) + r * NN;
        const float* xsrc = u + (size_t)(row0 + r) * DIN + h * 64;
#pragma unroll
        for (int i = 0; i < 4; i++) {
            int n = f0 + i * 4;
            float4 cv = *(const float4*)(csrc + n);
            float4 bv = *(const float4*)(bsrc + n);
            float4 hv = *(const float4*)(hsrc + n);
            Cs[(n+0)*T64 + r] = cv.x; Cs[(n+1)*T64 + r] = cv.y;
            Cs[(n+2)*T64 + r] = cv.z; Cs[(n+3)*T64 + r] = cv.w;
            Bsm[(n+0)*T64 + r] = bv.x; Bsm[(n+1)*T64 + r] = bv.y;
            Bsm[(n+2)*T64 + r] = bv.z; Bsm[(n+3)*T64 + r] = bv.w;
            hT[(n+0)*T64 + r] = hv.x; hT[(n+1)*T64 + r] = hv.y;
            hT[(n+2)*T64 + r] = hv.z; hT[(n+3)*T64 + r] = hv.w;
            *(float4*)&xs[r * T64 + n] = *(const float4*)(xsrc + n);
        }
    }
    __syncthreads();

    const int t0 = (tid >> 4) * 4, c0 = (tid & 15) * 4;  // c0 = s0 (phase A) / p0 (phase B)

    // Phase A: M[t][s] = C_t . B_s  (over n), f32x2 along s
    unsigned long long ma[4][2] = {};
#pragma unroll 8
    for (int n = 0; n < 64; n++) {
        float4 av = *(const float4*)&Cs[n * T64 + t0];
        ulonglong2 bv = *(const ulonglong2*)&Bsm[n * T64 + c0];
        float af[4] = {av.x, av.y, av.z, av.w};
#pragma unroll
        for (int i = 0; i < 4; i++) {
            unsigned long long a2 = pack2(af[i], af[i]);
            ma[i][0] = fma2(a2, bv.x, ma[i][0]);
            ma[i][1] = fma2(a2, bv.y, ma[i][1]);
        }
    }
    // mask + decay + dt fold; write transposed Ms[s][t]
    {
        float cdt[4];
#pragma unroll
        for (int i = 0; i < 4; i++) cdt[i] = sm_cd[t0 + i];
#pragma unroll
        for (int j = 0; j < 4; j++) {
            int s = c0 + j;
            float ds = sm_dt[s], cds = sm_cd[s];
            float col[4];
#pragma unroll
            for (int i = 0; i < 4; i++) {
                float2 pr = unpk(ma[i][j >> 1]);
                float m = (j & 1) ? pr.y : pr.x;
                int t = t0 + i;
                col[i] = (s <= t) ? m * ds * expf(A * (cdt[i] - cds)) : 0.f;
            }
            *(float4*)&Ms[s * T64 + t0] = make_float4(col[0], col[1], col[2], col[3]);
        }
    }
    __syncthreads();

    // Phase B: Y1 = Ms @ x  (over s),  Y2 = C @ hst^T  (over n)
    unsigned long long y1[4][2] = {}, y2[4][2] = {};
#pragma unroll 8
    for (int s = 0; s < 64; s++) {
        float4 av = *(const float4*)&Ms[s * T64 + t0];
        ulonglong2 bv = *(const ulonglong2*)&xs[s * T64 + c0];
        float af[4] = {av.x, av.y, av.z, av.w};
#pragma unroll
        for (int i = 0; i < 4; i++) {
            unsigned long long a2 = pack2(af[i], af[i]);
            y1[i][0] = fma2(a2, bv.x, y1[i][0]);
            y1[i][1] = fma2(a2, bv.y, y1[i][1]);
        }
    }
#pragma unroll 8
    for (int n = 0; n < 64; n++) {
        float4 av = *(const float4*)&Cs[n * T64 + t0];
        ulonglong2 bv = *(const ulonglong2*)&hT[n * T64 + c0];
        float af[4] = {av.x, av.y, av.z, av.w};
#pragma unroll
        for (int i = 0; i < 4; i++) {
            unsigned long long a2 = pack2(af[i], af[i]);
            y2[i][0] = fma2(a2, bv.x, y2[i][0]);
            y2[i][1] = fma2(a2, bv.y, y2[i][1]);
        }
    }

    // Epilogue: y = Y1 + exp(A*cd_t)*Y2 + Ds*x
    const float Dh = Ds[h];
#pragma unroll
    for (int i = 0; i < 4; i++) {
        int t = t0 + i;
        float et = expf(A * sm_cd[t]);
        float4 x4 = *(const float4*)&xs[t * T64 + c0];
        float2 a0 = unpk(y1[i][0]), a1 = unpk(y1[i][1]);
        float2 b0 = unpk(y2[i][0]), b1 = unpk(y2[i][1]);
        float4 o;
        o.x = fmaf(et, b0.x, a0.x) + Dh * x4.x;
        o.y = fmaf(et, b0.y, a0.y) + Dh * x4.y;
        o.z = fmaf(et, b1.x, a1.x) + Dh * x4.z;
        o.w = fmaf(et, b1.y, a1.y) + Dh * x4.w;
        *(float4*)(y + (size_t)(row0 + t) * DIN + h * 64 + c0) = o;
    }
}

// ---------------- launch ------------------------------------------------------
extern "C" void kernel_launch(void* const* d_in, const int* in_sizes, int n_in,
                              void* d_out, int out_size) {
    const float* src     = (const float*)d_in[0];
    const float* ln_w    = (const float*)d_in[1];
    const float* ln_b    = (const float*)d_in[2];
    const float* W_in    = (const float*)d_in[3];
    const float* conv_w  = (const float*)d_in[4];
    const float* conv_b  = (const float*)d_in[5];
    const float* W_xproj = (const float*)d_in[6];
    const float* dt_bias = (const float*)d_in[7];
    const float* A_log   = (const float*)d_in[8];
    const float* Ds      = (const float*)d_in[9];
    const float* oln_w   = (const float*)d_in[10];
    const float* oln_b   = (const float*)d_in[11];
    const float* W_out   = (const float*)d_in[12];
    float* out = (float*)d_out;

    float  *p_xln, *p_u0, *p_u, *p_dbc, *p_y, *p_yln, *p_S, *p_hst, *p_cdT;
    float2 *p_dd;
    cudaGetSymbolAddress((void**)&p_xln, g_xln);
    cudaGetSymbolAddress((void**)&p_u0,  g_u0);
    cudaGetSymbolAddress((void**)&p_u,   g_u);
    cudaGetSymbolAddress((void**)&p_dbc, g_dbc);
    cudaGetSymbolAddress((void**)&p_dd,  g_dd);
    cudaGetSymbolAddress((void**)&p_y,   g_y);
    cudaGetSymbolAddress((void**)&p_yln, g_yln);
    cudaGetSymbolAddress((void**)&p_S,   g_S);
    cudaGetSymbolAddress((void**)&p_hst, g_hst);
    cudaGetSymbolAddress((void**)&p_cdT, g_cdT);

    cudaFuncSetAttribute(mma_gemm<false,false>, cudaFuncAttributeMaxDynamicSharedMemorySize, GEMM_SMEM);
    cudaFuncSetAttribute(mma_gemm<false,true>,  cudaFuncAttributeMaxDynamicSharedMemorySize, GEMM_SMEM);
    cudaFuncSetAttribute(mma_gemm<true,false>,  cudaFuncAttributeMaxDynamicSharedMemorySize, GEMM_SMEM);
    cudaFuncSetAttribute(ssd_out, cudaFuncAttributeMaxDynamicSharedMemorySize, SSD3_SMEM);

    // 1. input LN
    ln_kernel<DD><<<ROWS, 256>>>(src, ln_w, ln_b, p_xln);
    // 2. u0 = xln @ W_in  (16384 x 512, K=256)
    mma_gemm<false,false><<<dim3(DIN/BN, ROWS/BM), 256, GEMM_SMEM>>>(
        p_xln, W_in, p_u0, nullptr, nullptr, nullptr, nullptr, ROWS, DIN, DD);
    // 3. depthwise conv3 + GELU
    conv_gelu_kernel<<<ROWS, DIN/4>>>(p_u0, conv_w, conv_b, p_u);
    // 4. dbc = u @ W_xproj (16384 x 136, K=512), dt/decay fused in epilogue
    mma_gemm<false,true><<<dim3((XPROJ_N + BN - 1)/BN, ROWS/BM), 256, GEMM_SMEM>>>(
        p_u, W_xproj, p_dbc, nullptr, dt_bias, A_log, p_dd, ROWS, XPROJ_N, DIN);
    // 5. SSD chunked scan
    ssd_prep<<<NBHK, 256>>>(p_u, p_dbc, p_dd, A_log, p_S, p_cdT);
    ssd_state<<<BB*HH, 256>>>(p_S, p_cdT, A_log, p_hst);
    ssd_out<<<NBHK, 256, SSD3_SMEM>>>(p_u, p_dbc, p_dd, A_log, Ds, p_hst, p_y);
    // 6. output LN
    ln_kernel<DIN><<<ROWS, 256>>>(p_y, oln_w, oln_b, p_yln);
    // 7. out = src + yln @ W_out (16384 x 256, K=512)
    mma_gemm<true,false><<<dim3(DD/BN, ROWS/BM), 256, GEMM_SMEM>>>(
        p_yln, W_out, out, src, nullptr, nullptr, nullptr, ROWS, DD, DIN);
}